// round 7
// baseline (speedup 1.0000x reference)
#include <cuda_runtime.h>
#include <cuda_fp16.h>
#include <math.h>
#include <stdint.h>

// ---------------------------------------------------------------------------
// B=2, T=24, H=256, W=256, N=512, HIDDEN=256
// conv1: im2col (K=147->160) + mma fp16 2-pass (W split)   -> feat1 fp16
// conv2: 3x3x64->128 s2  implicit GEMM mma fp16 2-pass     -> feat2 fp16
// conv3: 3x3x128->256 s2 implicit GEMM mma fp16 2-pass     -> feat3 fp32+fp16
// corr : [48] 512x1024x256 GEMM mma fp16 2-pass (Q split)
// ---------------------------------------------------------------------------

__device__ __half g_im2col[2 * 24 * 128 * 128 * 160];     // 252 MB
__device__ __half g_f1[2 * 24 * 128 * 128 * 64];          // 100 MB
__device__ __half g_f2[2 * 24 * 64 * 64 * 128];           //  50 MB
__device__ float  g_feat3[2 * 24 * 32 * 32 * 256];        //  50 MB (sampling)
__device__ __half g_f3[2 * 24 * 32 * 32 * 256];           //  25 MB (corr B)
__device__ __half g_qh[2 * 512 * 256], g_ql[2 * 512 * 256];
__device__ float  g_corr[2 * 24 * 512 * 1024];            // 100 MB
__device__ __half g_w1h[64 * 160],   g_w1l[64 * 160];
__device__ __half g_w2h[128 * 576],  g_w2l[128 * 576];
__device__ __half g_w3h[256 * 1152], g_w3l[256 * 1152];

// ---------------------------------------------------------------------------
// helpers
// ---------------------------------------------------------------------------
__device__ __forceinline__ uint32_t smem_u32(const void* p) {
    uint32_t a;
    asm("{ .reg .u64 t; cvta.to.shared.u64 t, %1; cvt.u32.u64 %0, t; }"
        : "=r"(a) : "l"(p));
    return a;
}

__device__ __forceinline__ void cp16(uint32_t dst, const void* gsrc, uint32_t ss) {
    asm volatile(
        "{ .reg .u64 g; cvta.to.global.u64 g, %1;"
        "  cp.async.ca.shared.global [%0], [g], 16, %2; }"
        :: "r"(dst), "l"(gsrc), "r"(ss) : "memory");
}
#define CP_COMMIT() asm volatile("cp.async.commit_group;" ::: "memory")
#define CP_WAIT1()  asm volatile("cp.async.wait_group 1;" ::: "memory")
#define CP_WAIT0()  asm volatile("cp.async.wait_group 0;" ::: "memory")

__device__ __forceinline__ void ldmx4(uint32_t* r, uint32_t addr) {
    asm volatile(
        "ldmatrix.sync.aligned.m8n8.x4.shared.b16 {%0,%1,%2,%3}, [%4];"
        : "=r"(r[0]), "=r"(r[1]), "=r"(r[2]), "=r"(r[3]) : "r"(addr));
}

__device__ __forceinline__ void mma_f16(float* d, const uint32_t* a,
                                        const uint32_t* b) {
    asm volatile(
        "mma.sync.aligned.m16n8k16.row.col.f32.f16.f16.f32 "
        "{%0,%1,%2,%3}, {%4,%5,%6,%7}, {%8,%9}, {%0,%1,%2,%3};"
        : "+f"(d[0]), "+f"(d[1]), "+f"(d[2]), "+f"(d[3])
        : "r"(a[0]), "r"(a[1]), "r"(a[2]), "r"(a[3]), "r"(b[0]), "r"(b[1]));
}

__device__ __forceinline__ uint32_t packh2(float a, float b) {
    __half2 t = __floats2half2_rn(a, b);
    return *reinterpret_cast<uint32_t*>(&t);
}

// smem tile: 128 rows x 32 fp16, row stride 80 B (16B pad, conflict-free)
#define RS    80
#define MATB  (128 * RS)            // 10240 B
#define STG3  (3 * MATB)            // A | Bh | Bl  (or Qh | Ql | X)
#define DSMEM_CONV (3 * STG3)       // 92160 B, 3-stage pipeline
// conv1: 3 A-stages + Bh(5 chunks x 64 rows x 80B) + Bl
#define C1_BH (3 * MATB)
#define C1_BL (C1_BH + 5 * 64 * RS)
#define DSMEM_C1 (C1_BL + 5 * 64 * RS)   // 81920 B

// ---------------------------------------------------------------------------
// im2col for conv1: video [bt][256][256][3] -> [px][160] fp16 (k=dy*21+dx*3+ci)
// thread = (px, dy); includes /255 scaling and SAME pad_lo=2 zero fill.
// ---------------------------------------------------------------------------
__global__ void __launch_bounds__(256) im2col1_kernel(const float* __restrict__ video)
{
    int gid = blockIdx.x * 256 + threadIdx.x;       // 786432*7
    int dy = gid % 7;
    int p  = gid / 7;
    int x  = p & 127;
    int y  = (p >> 7) & 127;
    int bt = p >> 14;
    int iy = 2 * y + dy - 2;
    bool vrow = (unsigned)iy < 256u;
    const float inv255 = 1.0f / 255.0f;

    __half* dst = g_im2col + (size_t)p * 160 + dy * 21;
    const float* src = video + (((size_t)bt * 256 + (vrow ? iy : 0)) * 256) * 3;

#pragma unroll
    for (int dx = 0; dx < 7; dx++) {
        int ix = 2 * x + dx - 2;
        bool v = vrow && ((unsigned)ix < 256u);
        float f0 = 0.f, f1 = 0.f, f2 = 0.f;
        if (v) {
            const float* q = src + ix * 3;
            f0 = q[0] * inv255; f1 = q[1] * inv255; f2 = q[2] * inv255;
        }
        dst[dx * 3 + 0] = __float2half(f0);
        dst[dx * 3 + 1] = __float2half(f1);
        dst[dx * 3 + 2] = __float2half(f2);
    }
    if (dy == 6) {
        __half* pad = g_im2col + (size_t)p * 160;
#pragma unroll
        for (int k = 147; k < 160; k++) pad[k] = __float2half(0.f);
    }
}

// ---------------------------------------------------------------------------
// weight prep: w1[k=147][64] -> w1t hi/lo [64][160] (zero padded)
// ---------------------------------------------------------------------------
__global__ void __launch_bounds__(256) prep_w1_kernel(const float* __restrict__ w)
{
    int i = blockIdx.x * 256 + threadIdx.x;   // 64*160
    if (i >= 64 * 160) return;
    int c = i / 160, k = i - c * 160;
    float v = (k < 147) ? w[k * 64 + c] : 0.f;
    __half hb = __float2half(v);
    g_w1h[i] = hb;
    g_w1l[i] = __float2half(v - __half2float(hb));
}

// w[k][cout] -> wt hi/lo [cout][k]
__global__ void __launch_bounds__(256) transpose_split_w(
    const float* __restrict__ w, __half* __restrict__ h,
    __half* __restrict__ l, int K, int C)
{
    int i = blockIdx.x * 256 + threadIdx.x;
    if (i < K * C) {
        int k = i / C, c = i - k * C;
        float v = w[i];
        __half hb = __float2half(v);
        h[(size_t)c * K + k] = hb;
        l[(size_t)c * K + k] = __float2half(v - __half2float(hb));
    }
}

// ---------------------------------------------------------------------------
// conv1 GEMM: [786432 x 64] = im2col[786432 x 160] . w1t^T, fp16 2-pass.
// Block 128(M) x 64(N); 8 warps = 4M x 2N, warp tile 32x32. B preloaded.
// ---------------------------------------------------------------------------
__global__ void __launch_bounds__(256, 2) conv1_gemm_kernel(
    const float* __restrict__ bias)
{
    extern __shared__ char sm[];
    __shared__ float s_bias[64];

    int tid  = threadIdx.x;
    int lane = tid & 31;
    int wid  = tid >> 5;
    int wm   = wid & 3;
    int wn   = wid >> 2;

    if (tid < 64) s_bias[tid] = bias[tid];

    uint32_t smb = smem_u32(sm);

    // B preload: 2 mats (hi/lo) x 5 chunks x 64 rows x 4 segs of 8 halfs
    // = 2560 cp16 transfers. Row layout: chunk cc -> smem rows [cc*64, cc*64+64)
    for (int u = tid; u < 2560; u += 256) {
        int part = u / 1280;              // 0 = hi, 1 = lo
        int uu   = u - part * 1280;
        int seg  = uu & 3;                // 8-half segment within row
        int cc   = (uu >> 2) % 5;         // K chunk
        int r    = uu / 20;               // cout row
        const __half* s = (part ? g_w1l : g_w1h) + r * 160 + cc * 32 + seg * 8;
        uint32_t d = smb + (part ? C1_BL : C1_BH) + (cc * 64 + r) * RS + seg * 16;
        cp16(d, s, 16u);
    }

    // A fill: 2 threads per row
    int fr = tid >> 1;
    int fo = (tid & 1) * 16;
    int p  = blockIdx.x * 128 + fr;
    const __half* arow = g_im2col + (size_t)p * 160 + fo;

    int aoff = ((((lane >> 3) & 1) * 8 + (lane & 7)) * RS) + ((lane >> 4) * 8) * 2;
    int boff = (((lane >> 4) * 8 + (lane & 7)) * RS) + (((lane >> 3) & 1) * 8) * 2;

    float acc[2][4][4];
#pragma unroll
    for (int i = 0; i < 2; i++)
#pragma unroll
        for (int j = 0; j < 4; j++)
#pragma unroll
            for (int k = 0; k < 4; k++) acc[i][j][k] = 0.0f;

    auto FILL = [&](int s, int kt) {
        uint32_t d = smb + s * MATB + fr * RS + fo * 2;
        cp16(d,      arow + kt * 32,     16u);
        cp16(d + 16, arow + kt * 32 + 8, 16u);
    };

    auto COMPUTE = [&](int s, int kt) {
        uint32_t ab = smb + s * MATB;
        uint32_t bb = kt * (64 * RS);
#pragma unroll
        for (int ks = 0; ks < 2; ks++) {
            uint32_t bh[8], bl[8];
#pragma unroll
            for (int q = 0; q < 2; q++) {
                uint32_t ro = boff + (wn * 32 + q * 16) * RS + ks * 32 + bb;
                ldmx4(&bh[4 * q], smb + C1_BH + ro);
                ldmx4(&bl[4 * q], smb + C1_BL + ro);
            }
#pragma unroll
            for (int mt = 0; mt < 2; mt++) {
                uint32_t af[4];
                ldmx4(af, ab + aoff + (wm * 32 + mt * 16) * RS + ks * 32);
#pragma unroll
                for (int nt = 0; nt < 4; nt++) mma_f16(acc[mt][nt], af, &bh[2 * nt]);
#pragma unroll
                for (int nt = 0; nt < 4; nt++) mma_f16(acc[mt][nt], af, &bl[2 * nt]);
            }
        }
    };

    FILL(0, 0); CP_COMMIT();       // group 0: B preload + A stage 0
    FILL(1, 1); CP_COMMIT();       // group 1: A stage 1
#pragma unroll 1
    for (int kt = 0; kt < 5; kt++) {
        if (kt + 1 < 5) { CP_WAIT1(); } else { CP_WAIT0(); }
        __syncthreads();
        if (kt + 2 < 5) { FILL((kt + 2) % 3, kt + 2); CP_COMMIT(); }
        COMPUTE(kt % 3, kt);
    }

    int mrow = blockIdx.x * 128 + wm * 32 + (lane >> 2);
    int cbase = wn * 32 + 2 * (lane & 3);
#pragma unroll
    for (int mt = 0; mt < 2; mt++) {
#pragma unroll
        for (int nt = 0; nt < 4; nt++) {
            int col = cbase + nt * 8;
            float b0 = s_bias[col], b1 = s_bias[col + 1];
            size_t r0 = (size_t)(mrow + mt * 16) * 64 + col;
            size_t r1 = (size_t)(mrow + mt * 16 + 8) * 64 + col;
            float a0 = fmaxf(acc[mt][nt][0] + b0, 0.f);
            float a1 = fmaxf(acc[mt][nt][1] + b1, 0.f);
            float a2 = fmaxf(acc[mt][nt][2] + b0, 0.f);
            float a3 = fmaxf(acc[mt][nt][3] + b1, 0.f);
            *reinterpret_cast<uint32_t*>(g_f1 + r0) = packh2(a0, a1);
            *reinterpret_cast<uint32_t*>(g_f1 + r1) = packh2(a2, a3);
        }
    }
}

// ---------------------------------------------------------------------------
// Implicit-GEMM 3x3 s2 conv, fp16 2-pass (A single, B=weights hi/lo).
// Block tile 128 x 128, K chunk 32, 8 warps (2M x 4N), 3-stage cp.async.
// ---------------------------------------------------------------------------
template <int CIN, int COUT, int HIN, int WIN, int HOUT, int WOUT, bool WF32>
__global__ void __launch_bounds__(256, 2) conv_mma_kernel(
    const __half* __restrict__ in,
    const __half* __restrict__ wth,
    const __half* __restrict__ wtl,
    const float* __restrict__ bias,
    __half* __restrict__ outh,
    float* __restrict__ outf)
{
    extern __shared__ char sm[];
    __shared__ float s_bias[128];

    const int KTOT = 9 * CIN;
    const int CPP  = CIN / 32;
    const int NT   = 9 * CPP;

    int tid  = threadIdx.x;
    int lane = tid & 31;
    int wid  = tid >> 5;
    int wm   = wid & 1;
    int wn   = wid >> 1;
    int cobase = blockIdx.y * 128;

    if (tid < 128) s_bias[tid] = bias[cobase + tid];

    int fr = tid >> 1;
    int fo = (tid & 1) * 16;
    int p  = blockIdx.x * 128 + fr;
    int fx = p % WOUT;
    int fy = (p / WOUT) % HOUT;
    int fbt = p / (WOUT * HOUT);
    const __half* bsh = wth + (size_t)(cobase + fr) * KTOT + fo;
    const __half* bsl = wtl + (size_t)(cobase + fr) * KTOT + fo;

    uint32_t smb = smem_u32(sm);

    int aoff = ((((lane >> 3) & 1) * 8 + (lane & 7)) * RS) + ((lane >> 4) * 8) * 2;
    int boff = (((lane >> 4) * 8 + (lane & 7)) * RS) + (((lane >> 3) & 1) * 8) * 2;

    float acc[4][4][4];
#pragma unroll
    for (int i = 0; i < 4; i++)
#pragma unroll
        for (int j = 0; j < 4; j++)
#pragma unroll
            for (int k = 0; k < 4; k++) acc[i][j][k] = 0.0f;

    auto FILL = [&](int s, int kt) {
        int pos = kt / CPP, ci0 = (kt - pos * CPP) * 32;
        int dy = pos / 3, dx = pos - dy * 3;
        int iy = 2 * fy + dy, ix = 2 * fx + dx;
        bool valid = (iy < HIN) && (ix < WIN);
        uint32_t vs = valid ? 16u : 0u;
        size_t asrc = valid
            ? ((((size_t)fbt * HIN + iy) * WIN + ix) * CIN + ci0 + fo) : 0;
        uint32_t d = smb + s * STG3 + fr * RS + fo * 2;
        cp16(d,                 in + asrc,         vs);
        cp16(d + 16,            in + asrc + 8,     vs);
        cp16(d + MATB,          bsh + kt * 32,     16u);
        cp16(d + MATB + 16,     bsh + kt * 32 + 8, 16u);
        cp16(d + 2 * MATB,      bsl + kt * 32,     16u);
        cp16(d + 2 * MATB + 16, bsl + kt * 32 + 8, 16u);
    };

    auto COMPUTE = [&](int s) {
        uint32_t ab = smb + s * STG3;
#pragma unroll
        for (int ks = 0; ks < 2; ks++) {
            uint32_t bh[8], bl[8];
#pragma unroll
            for (int q = 0; q < 2; q++) {
                uint32_t ro = boff + (wn * 32 + q * 16) * RS + ks * 32;
                ldmx4(&bh[4 * q], ab + MATB + ro);
                ldmx4(&bl[4 * q], ab + 2 * MATB + ro);
            }
#pragma unroll
            for (int mt = 0; mt < 4; mt++) {
                uint32_t af[4];
                ldmx4(af, ab + aoff + (wm * 64 + mt * 16) * RS + ks * 32);
#pragma unroll
                for (int nt = 0; nt < 4; nt++) mma_f16(acc[mt][nt], af, &bh[2 * nt]);
#pragma unroll
                for (int nt = 0; nt < 4; nt++) mma_f16(acc[mt][nt], af, &bl[2 * nt]);
            }
        }
    };

    FILL(0, 0); CP_COMMIT();
    FILL(1, 1); CP_COMMIT();
#pragma unroll 1
    for (int kt = 0; kt < NT; kt++) {
        if (kt + 1 < NT) { CP_WAIT1(); } else { CP_WAIT0(); }
        __syncthreads();
        if (kt + 2 < NT) { FILL((kt + 2) % 3, kt + 2); CP_COMMIT(); }
        COMPUTE(kt % 3);
    }

    int mrow = blockIdx.x * 128 + wm * 64 + (lane >> 2);
    int cbase = wn * 32 + 2 * (lane & 3);
#pragma unroll
    for (int mt = 0; mt < 4; mt++) {
#pragma unroll
        for (int nt = 0; nt < 4; nt++) {
            int col = cbase + nt * 8;
            float b0 = s_bias[col], b1 = s_bias[col + 1];
            size_t r0 = (size_t)(mrow + mt * 16) * COUT + cobase + col;
            size_t r1 = (size_t)(mrow + mt * 16 + 8) * COUT + cobase + col;
            float a0 = fmaxf(acc[mt][nt][0] + b0, 0.f);
            float a1 = fmaxf(acc[mt][nt][1] + b1, 0.f);
            float a2 = fmaxf(acc[mt][nt][2] + b0, 0.f);
            float a3 = fmaxf(acc[mt][nt][3] + b1, 0.f);
            *reinterpret_cast<uint32_t*>(outh + r0) = packh2(a0, a1);
            *reinterpret_cast<uint32_t*>(outh + r1) = packh2(a2, a3);
            if (WF32) {
                *reinterpret_cast<float2*>(outf + r0) = make_float2(a0, a1);
                *reinterpret_cast<float2*>(outf + r1) = make_float2(a2, a3);
            }
        }
    }
}

// ---------------------------------------------------------------------------
// corr GEMM: D = Q . X^T / 16; Q split hi/lo fp16 (A side), X single fp16.
// ---------------------------------------------------------------------------
__global__ void __launch_bounds__(256, 2) corr_mma_kernel()
{
    extern __shared__ char sm[];

    int tid  = threadIdx.x;
    int lane = tid & 31;
    int wid  = tid >> 5;
    int wm   = wid & 1;
    int wn   = wid >> 1;

    int bt  = blockIdx.z;
    int b   = bt / 24;
    int n0  = blockIdx.y * 128;
    int hw0 = blockIdx.x * 128;

    int fr = tid >> 1;
    int fo = (tid & 1) * 16;
    const __half* ah = g_qh + ((size_t)b * 512 + n0 + fr) * 256 + fo;
    const __half* al = g_ql + ((size_t)b * 512 + n0 + fr) * 256 + fo;
    const __half* bx = g_f3 + ((size_t)bt * 1024 + hw0 + fr) * 256 + fo;

    uint32_t smb = smem_u32(sm);

    int aoff = ((((lane >> 3) & 1) * 8 + (lane & 7)) * RS) + ((lane >> 4) * 8) * 2;
    int boff = (((lane >> 4) * 8 + (lane & 7)) * RS) + (((lane >> 3) & 1) * 8) * 2;

    float acc[4][4][4];
#pragma unroll
    for (int i = 0; i < 4; i++)
#pragma unroll
        for (int j = 0; j < 4; j++)
#pragma unroll
            for (int k = 0; k < 4; k++) acc[i][j][k] = 0.0f;

    auto FILL = [&](int s, int kt) {
        uint32_t d = smb + s * STG3 + fr * RS + fo * 2;
        cp16(d,                 ah + kt * 32,     16u);
        cp16(d + 16,            ah + kt * 32 + 8, 16u);
        cp16(d + MATB,          al + kt * 32,     16u);
        cp16(d + MATB + 16,     al + kt * 32 + 8, 16u);
        cp16(d + 2 * MATB,      bx + kt * 32,     16u);
        cp16(d + 2 * MATB + 16, bx + kt * 32 + 8, 16u);
    };

    auto COMPUTE = [&](int s) {
        uint32_t ab = smb + s * STG3;
#pragma unroll
        for (int ks = 0; ks < 2; ks++) {
            uint32_t bxr[8];
#pragma unroll
            for (int q = 0; q < 2; q++) {
                uint32_t ro = boff + (wn * 32 + q * 16) * RS + ks * 32;
                ldmx4(&bxr[4 * q], ab + 2 * MATB + ro);
            }
#pragma unroll
            for (int mt = 0; mt < 4; mt++) {
                uint32_t af[4];
                uint32_t aaddr = ab + aoff + (wm * 64 + mt * 16) * RS + ks * 32;
                ldmx4(af, aaddr);
#pragma unroll
                for (int nt = 0; nt < 4; nt++) mma_f16(acc[mt][nt], af, &bxr[2 * nt]);
                ldmx4(af, aaddr + MATB);
#pragma unroll
                for (int nt = 0; nt < 4; nt++) mma_f16(acc[mt][nt], af, &bxr[2 * nt]);
            }
        }
    };

    FILL(0, 0); CP_COMMIT();
    FILL(1, 1); CP_COMMIT();
#pragma unroll 1
    for (int kt = 0; kt < 8; kt++) {
        if (kt + 1 < 8) { CP_WAIT1(); } else { CP_WAIT0(); }
        __syncthreads();
        if (kt + 2 < 8) { FILL((kt + 2) % 3, kt + 2); CP_COMMIT(); }
        COMPUTE(kt % 3);
    }

    float* C = g_corr + (size_t)bt * 512 * 1024;
    int mrow = n0 + wm * 64 + (lane >> 2);
    int cbase = hw0 + wn * 32 + 2 * (lane & 3);
#pragma unroll
    for (int mt = 0; mt < 4; mt++) {
#pragma unroll
        for (int nt = 0; nt < 4; nt++) {
            int col = cbase + nt * 8;
            int r0 = mrow + mt * 16;
            float2 o0, o1;
            o0.x = acc[mt][nt][0] * 0.0625f;
            o0.y = acc[mt][nt][1] * 0.0625f;
            o1.x = acc[mt][nt][2] * 0.0625f;
            o1.y = acc[mt][nt][3] * 0.0625f;
            *reinterpret_cast<float2*>(C + (size_t)r0 * 1024 + col) = o0;
            *reinterpret_cast<float2*>(C + (size_t)(r0 + 8) * 1024 + col) = o1;
        }
    }
}

// ---------------------------------------------------------------------------
// Bilinear sampling -> q fp16 hi/lo
// ---------------------------------------------------------------------------
__global__ void __launch_bounds__(256) sample_kernel(const float* __restrict__ qp)
{
    int bn = blockIdx.x;
    float q0 = qp[bn * 3 + 0];
    float q1 = qp[bn * 3 + 1];
    float q2 = qp[bn * 3 + 2];

    int t = (int)(q0 * 23.0f);
    t = min(max(t, 0), 23);
    float yf = q1 * 31.0f;
    float xf = q2 * 31.0f;
    int y0 = min(max((int)floorf(yf), 0), 31);
    int y1 = min(y0 + 1, 31);
    int x0 = min(max((int)floorf(xf), 0), 31);
    int x1 = min(x0 + 1, 31);
    float wy1 = yf - (float)y0, wy0 = 1.0f - wy1;
    float wx1 = xf - (float)x0, wx0 = 1.0f - wx1;

    int b = bn >> 9;
    const float* f = g_feat3 + (size_t)(b * 24 + t) * 1024 * 256;
    int c = threadIdx.x;
    float f00 = f[(size_t)(y0 * 32 + x0) * 256 + c];
    float f01 = f[(size_t)(y0 * 32 + x1) * 256 + c];
    float f10 = f[(size_t)(y1 * 32 + x0) * 256 + c];
    float f11 = f[(size_t)(y1 * 32 + x1) * 256 + c];
    float f0 = f00 * wx0 + f01 * wx1;
    float f1 = f10 * wx0 + f11 * wx1;
    float v = f0 * wy0 + f1 * wy1;
    __half hb = __float2half(v);
    g_qh[(size_t)bn * 256 + c] = hb;
    g_ql[(size_t)bn * 256 + c] = __float2half(v - __half2float(hb));
}

// ---------------------------------------------------------------------------
// Fused softmax(corr*10) expectation + occlusion.
// ---------------------------------------------------------------------------
__global__ void __launch_bounds__(256) finalize_kernel(float* __restrict__ out)
{
    int gwarp = (blockIdx.x * 256 + threadIdx.x) >> 5;
    int lane  = threadIdx.x & 31;

    const float* c = g_corr + (size_t)gwarp * 1024;
    float v[32];
    float m = -1e30f;
#pragma unroll
    for (int i = 0; i < 8; i++) {
        float4 t4 = *reinterpret_cast<const float4*>(&c[i * 128 + lane * 4]);
        v[i * 4 + 0] = t4.x;
        v[i * 4 + 1] = t4.y;
        v[i * 4 + 2] = t4.z;
        v[i * 4 + 3] = t4.w;
        m = fmaxf(m, fmaxf(fmaxf(t4.x, t4.y), fmaxf(t4.z, t4.w)));
    }
#pragma unroll
    for (int o = 16; o > 0; o >>= 1)
        m = fmaxf(m, __shfl_xor_sync(0xffffffffu, m, o));

    float s = 0.0f, sx = 0.0f, sy = 0.0f;
#pragma unroll
    for (int i = 0; i < 8; i++) {
#pragma unroll
        for (int j = 0; j < 4; j++) {
            int idx = i * 128 + lane * 4 + j;
            float e = __expf(10.0f * (v[i * 4 + j] - m));
            s  += e;
            sx += e * (float)(idx & 31);
            sy += e * (float)(idx >> 5);
        }
    }
#pragma unroll
    for (int o = 16; o > 0; o >>= 1) {
        s  += __shfl_xor_sync(0xffffffffu, s, o);
        sx += __shfl_xor_sync(0xffffffffu, sx, o);
        sy += __shfl_xor_sync(0xffffffffu, sy, o);
    }

    if (lane == 0) {
        int bt = gwarp >> 9;
        int n  = gwarp & 511;
        int b  = bt / 24;
        int t  = bt - b * 24;
        int o  = (b * 512 + n) * 24 + t;
        float inv = 8.0f / s;
        out[2 * o + 0] = sx * inv;
        out[2 * o + 1] = sy * inv;
        out[2 * 24576 + o] = 1.0f / (1.0f + __expf(m));
    }
}

// ---------------------------------------------------------------------------
// Launch
// ---------------------------------------------------------------------------
extern "C" void kernel_launch(void* const* d_in, const int* in_sizes, int n_in,
                              void* d_out, int out_size)
{
    const float* video = (const float*)d_in[0];
    const float* qp    = (const float*)d_in[1];
    const float* w1    = (const float*)d_in[2];
    const float* b1    = (const float*)d_in[3];
    const float* w2    = (const float*)d_in[4];
    const float* b2    = (const float*)d_in[5];
    const float* w3    = (const float*)d_in[6];
    const float* b3    = (const float*)d_in[7];

    __half *f1, *f2, *f3, *wt2h, *wt2l, *wt3h, *wt3l;
    float *feat3;
    cudaGetSymbolAddress((void**)&f1, g_f1);
    cudaGetSymbolAddress((void**)&f2, g_f2);
    cudaGetSymbolAddress((void**)&f3, g_f3);
    cudaGetSymbolAddress((void**)&feat3, g_feat3);
    cudaGetSymbolAddress((void**)&wt2h, g_w2h);
    cudaGetSymbolAddress((void**)&wt2l, g_w2l);
    cudaGetSymbolAddress((void**)&wt3h, g_w3h);
    cudaGetSymbolAddress((void**)&wt3l, g_w3l);

    cudaFuncSetAttribute((const void*)conv1_gemm_kernel,
                         cudaFuncAttributeMaxDynamicSharedMemorySize, DSMEM_C1);
    cudaFuncSetAttribute(
        (const void*)conv_mma_kernel<64, 128, 128, 128, 64, 64, false>,
        cudaFuncAttributeMaxDynamicSharedMemorySize, DSMEM_CONV);
    cudaFuncSetAttribute(
        (const void*)conv_mma_kernel<128, 256, 64, 64, 32, 32, true>,
        cudaFuncAttributeMaxDynamicSharedMemorySize, DSMEM_CONV);
    cudaFuncSetAttribute((const void*)corr_mma_kernel,
                         cudaFuncAttributeMaxDynamicSharedMemorySize, DSMEM_CONV);

    // weight prep (tiny)
    prep_w1_kernel<<<40, 256>>>(w1);
    transpose_split_w<<<(576 * 128 + 255) / 256, 256>>>(w2, wt2h, wt2l, 576, 128);
    transpose_split_w<<<(1152 * 256 + 255) / 256, 256>>>(w3, wt3h, wt3l, 1152, 256);

    // conv1: im2col + GEMM
    im2col1_kernel<<<21504, 256>>>(video);
    conv1_gemm_kernel<<<6144, 256, DSMEM_C1>>>(b1);

    // conv2: 196608 px / 128 = 1536 tiles
    conv_mma_kernel<64, 128, 128, 128, 64, 64, false>
        <<<dim3(1536, 1, 1), 256, DSMEM_CONV>>>(f1, wt2h, wt2l, b2, f2, nullptr);

    // conv3: 384 tiles x 2 N-chunks
    conv_mma_kernel<128, 256, 64, 64, 32, 32, true>
        <<<dim3(384, 2, 1), 256, DSMEM_CONV>>>(f2, wt3h, wt3l, b3, f3, feat3);

    // sampling -> q hi/lo
    sample_kernel<<<1024, 256>>>(qp);

    // corr GEMM
    corr_mma_kernel<<<dim3(8, 4, 48), 256, DSMEM_CONV>>>();

    // softmax + expectation + occlusion
    finalize_kernel<<<3072, 256>>>((float*)d_out);
}

// round 8
// speedup vs baseline: 2.0021x; 2.0021x over previous
#include <cuda_runtime.h>
#include <cuda_fp16.h>
#include <math.h>
#include <stdint.h>

// ---------------------------------------------------------------------------
// B=2, T=24, H=256, W=256, N=512, HIDDEN=256
// conv1: FUSED smem-im2col + mma fp16 (W single)            -> feat1 fp16
// conv2: 3x3x64->128 s2  implicit GEMM mma fp16 2-pass      -> feat2 fp16
// conv3: 3x3x128->256 s2 implicit GEMM mma fp16 2-pass      -> feat3 fp32+fp16
// corr : [48] 512x1024x256 GEMM mma fp16 2-pass (Q split)
// ---------------------------------------------------------------------------

__device__ __half g_f1[2 * 24 * 128 * 128 * 64];          // 100 MB
__device__ __half g_f2[2 * 24 * 64 * 64 * 128];           //  50 MB
__device__ float  g_feat3[2 * 24 * 32 * 32 * 256];        //  50 MB (sampling)
__device__ __half g_f3[2 * 24 * 32 * 32 * 256];           //  25 MB (corr B)
__device__ __half g_qh[2 * 512 * 256], g_ql[2 * 512 * 256];
__device__ float  g_corr[2 * 24 * 512 * 1024];            // 100 MB
__device__ __half g_w1h[64 * 224];                        // conv1 W [cout][224]
__device__ __half g_w2h[128 * 576],  g_w2l[128 * 576];
__device__ __half g_w3h[256 * 1152], g_w3l[256 * 1152];

// ---------------------------------------------------------------------------
// helpers
// ---------------------------------------------------------------------------
__device__ __forceinline__ uint32_t smem_u32(const void* p) {
    uint32_t a;
    asm("{ .reg .u64 t; cvta.to.shared.u64 t, %1; cvt.u32.u64 %0, t; }"
        : "=r"(a) : "l"(p));
    return a;
}

__device__ __forceinline__ void cp16(uint32_t dst, const void* gsrc, uint32_t ss) {
    asm volatile(
        "{ .reg .u64 g; cvta.to.global.u64 g, %1;"
        "  cp.async.ca.shared.global [%0], [g], 16, %2; }"
        :: "r"(dst), "l"(gsrc), "r"(ss) : "memory");
}
#define CP_COMMIT() asm volatile("cp.async.commit_group;" ::: "memory")
#define CP_WAIT1()  asm volatile("cp.async.wait_group 1;" ::: "memory")
#define CP_WAIT0()  asm volatile("cp.async.wait_group 0;" ::: "memory")

__device__ __forceinline__ void ldmx4(uint32_t* r, uint32_t addr) {
    asm volatile(
        "ldmatrix.sync.aligned.m8n8.x4.shared.b16 {%0,%1,%2,%3}, [%4];"
        : "=r"(r[0]), "=r"(r[1]), "=r"(r[2]), "=r"(r[3]) : "r"(addr));
}

__device__ __forceinline__ void mma_f16(float* d, const uint32_t* a,
                                        const uint32_t* b) {
    asm volatile(
        "mma.sync.aligned.m16n8k16.row.col.f32.f16.f16.f32 "
        "{%0,%1,%2,%3}, {%4,%5,%6,%7}, {%8,%9}, {%0,%1,%2,%3};"
        : "+f"(d[0]), "+f"(d[1]), "+f"(d[2]), "+f"(d[3])
        : "r"(a[0]), "r"(a[1]), "r"(a[2]), "r"(a[3]), "r"(b[0]), "r"(b[1]));
}

__device__ __forceinline__ uint32_t packh2(float a, float b) {
    __half2 t = __floats2half2_rn(a, b);
    return *reinterpret_cast<uint32_t*>(&t);
}

// smem tile: 128 rows x 32 fp16, row stride 80 B (16B pad, conflict-free)
#define RS    80
#define MATB  (128 * RS)            // 10240 B
#define STG3  (3 * MATB)            // A | Bh | Bl  (or Qh | Ql | X)
#define DSMEM_CONV (3 * STG3)       // 92160 B, 3-stage pipeline

// conv1 fused smem layout:
//   A double buffer: 2 x MATB
//   B (weights, 7 chunks x 64 rows x RS)
//   V (video rows: 7 x 800 halfs = 7 x 1600 B)
#define C1_B   (2 * MATB)                 // 20480
#define C1_V   (C1_B + 7 * 64 * RS)       // 56320
#define C1_VROW 1600                      // bytes per padded video row
#define DSMEM_C1 (C1_V + 7 * C1_VROW)     // 67520

// ---------------------------------------------------------------------------
// conv1 weight prep: w1[(dy*7+dx)*3+ci][64] -> g_w1h[cout][dy*32 + dx*3+ci]
// slots r in [21,32) per tap are zero.
// ---------------------------------------------------------------------------
__global__ void __launch_bounds__(256) prep_w1_kernel(const float* __restrict__ w)
{
    int i = blockIdx.x * 256 + threadIdx.x;   // 64*224
    if (i >= 64 * 224) return;
    int c = i / 224, kk = i - c * 224;
    int dy = kk / 32, r = kk - dy * 32;
    float v = (r < 21) ? w[(dy * 21 + r) * 64 + c] : 0.f;
    g_w1h[i] = __float2half(v);
}

// w[k][cout] -> wt hi/lo [cout][k]
__global__ void __launch_bounds__(256) transpose_split_w(
    const float* __restrict__ w, __half* __restrict__ h,
    __half* __restrict__ l, int K, int C)
{
    int i = blockIdx.x * 256 + threadIdx.x;
    if (i < K * C) {
        int k = i / C, c = i - k * C;
        float v = w[i];
        __half hb = __float2half(v);
        h[(size_t)c * K + k] = hb;
        l[(size_t)c * K + k] = __float2half(v - __half2float(hb));
    }
}

// ---------------------------------------------------------------------------
// conv1 fused: one block = one output row (bt, y) = 128 pixels (M).
// N=64 couts. K = 7 taps x 32 (21 real). Video rows staged in smem with
// 2-pixel halo; A tile built from smem (contiguous copy); W single fp16.
// ---------------------------------------------------------------------------
__global__ void __launch_bounds__(256, 2) conv1_fused_kernel(
    const float* __restrict__ video,
    const float* __restrict__ bias)
{
    extern __shared__ char sm[];
    __shared__ float s_bias[64];

    int tid  = threadIdx.x;
    int lane = tid & 31;
    int wid  = tid >> 5;
    int wm   = wid & 3;          // 4 M-warps (32 rows each)
    int wn   = wid >> 2;         // 2 N-warps (32 cols each)

    int y  = blockIdx.x & 127;
    int bt = blockIdx.x >> 7;

    if (tid < 64) s_bias[tid] = bias[tid];

    uint32_t smb = smem_u32(sm);

    // --- B preload via cp.async: 7 chunks x 64 rows x 4 segs = 1792 cp16 ---
    for (int u = tid; u < 1792; u += 256) {
        int seg = u & 3;
        int cc  = (u >> 2) % 7;
        int r   = u / 28;
        const __half* s = g_w1h + r * 224 + cc * 32 + seg * 8;
        uint32_t d = smb + C1_B + (cc * 64 + r) * RS + seg * 16;
        cp16(d, s, 16u);
    }
    CP_COMMIT();

    // --- zero video smem (incl. halos), then fill rows ---
    uint32_t* vz = reinterpret_cast<uint32_t*>(sm + C1_V);
    for (int u = tid; u < 7 * C1_VROW / 4; u += 256) vz[u] = 0u;
    __syncthreads();

    // video rows: dy in [0,7), iy = 2y+dy-2; 768 floats -> halfs [6..773]
    const float inv255 = 1.0f / 255.0f;
    for (int u = tid; u < 7 * 384; u += 256) {
        int dy = u / 384;
        int m  = u - dy * 384;
        int iy = 2 * y + dy - 2;
        if ((unsigned)iy < 256u) {
            const float2 v2 = *reinterpret_cast<const float2*>(
                video + ((size_t)(bt * 256 + iy) * 256) * 3 + 2 * m);
            uint32_t pk = packh2(v2.x * inv255, v2.y * inv255);
            *reinterpret_cast<uint32_t*>(sm + C1_V + dy * C1_VROW + 12 + 4 * m) = pk;
        }
    }
    CP_WAIT0();
    __syncthreads();

    // --- A build: thread (fr=px, fo=0/16) copies 16 contiguous halfs ---
    int fr = tid >> 1;
    int fo = (tid & 1) * 16;

    auto BUILD = [&](int s, int dy) {
        // src: vsm[dy] halfs [6x+fo .. 6x+fo+15]  (x = fr)
        const uint32_t* src = reinterpret_cast<const uint32_t*>(
            sm + C1_V + dy * C1_VROW + (6 * fr + fo) * 2);
        uint32_t* dst = reinterpret_cast<uint32_t*>(
            sm + s * MATB + fr * RS + fo * 2);
#pragma unroll
        for (int j = 0; j < 8; j++) dst[j] = src[j];
    };

    int aoff = ((((lane >> 3) & 1) * 8 + (lane & 7)) * RS) + ((lane >> 4) * 8) * 2;
    int boff = (((lane >> 4) * 8 + (lane & 7)) * RS) + (((lane >> 3) & 1) * 8) * 2;

    float acc[2][4][4];
#pragma unroll
    for (int i = 0; i < 2; i++)
#pragma unroll
        for (int j = 0; j < 4; j++)
#pragma unroll
            for (int k = 0; k < 4; k++) acc[i][j][k] = 0.0f;

    auto COMPUTE = [&](int s, int cc) {
        uint32_t ab = smb + s * MATB;
        uint32_t bb = smb + C1_B + cc * (64 * RS);
#pragma unroll
        for (int ks = 0; ks < 2; ks++) {
            uint32_t bh[8];
#pragma unroll
            for (int q = 0; q < 2; q++) {
                uint32_t ro = boff + (wn * 32 + q * 16) * RS + ks * 32;
                ldmx4(&bh[4 * q], bb + ro);
            }
#pragma unroll
            for (int mt = 0; mt < 2; mt++) {
                uint32_t af[4];
                ldmx4(af, ab + aoff + (wm * 32 + mt * 16) * RS + ks * 32);
#pragma unroll
                for (int nt = 0; nt < 4; nt++) mma_f16(acc[mt][nt], af, &bh[2 * nt]);
            }
        }
    };

    BUILD(0, 0);
    __syncthreads();
#pragma unroll 1
    for (int cc = 0; cc < 7; cc++) {
        if (cc + 1 < 7) BUILD((cc + 1) & 1, cc + 1);
        COMPUTE(cc & 1, cc);
        __syncthreads();
    }

    // epilogue: bias + relu -> g_f1 fp16
    int mrow = blockIdx.x * 128 + wm * 32 + (lane >> 2);
    int cbase = wn * 32 + 2 * (lane & 3);
#pragma unroll
    for (int mt = 0; mt < 2; mt++) {
#pragma unroll
        for (int nt = 0; nt < 4; nt++) {
            int col = cbase + nt * 8;
            float b0 = s_bias[col], b1 = s_bias[col + 1];
            size_t r0 = (size_t)(mrow + mt * 16) * 64 + col;
            size_t r1 = (size_t)(mrow + mt * 16 + 8) * 64 + col;
            float a0 = fmaxf(acc[mt][nt][0] + b0, 0.f);
            float a1 = fmaxf(acc[mt][nt][1] + b1, 0.f);
            float a2 = fmaxf(acc[mt][nt][2] + b0, 0.f);
            float a3 = fmaxf(acc[mt][nt][3] + b1, 0.f);
            *reinterpret_cast<uint32_t*>(g_f1 + r0) = packh2(a0, a1);
            *reinterpret_cast<uint32_t*>(g_f1 + r1) = packh2(a2, a3);
        }
    }
}

// ---------------------------------------------------------------------------
// Implicit-GEMM 3x3 s2 conv, fp16 2-pass (A single, B=weights hi/lo).
// Block tile 128 x 128, K chunk 32, 8 warps (2M x 4N), 3-stage cp.async.
// ---------------------------------------------------------------------------
template <int CIN, int COUT, int HIN, int WIN, int HOUT, int WOUT, bool WF32>
__global__ void __launch_bounds__(256, 2) conv_mma_kernel(
    const __half* __restrict__ in,
    const __half* __restrict__ wth,
    const __half* __restrict__ wtl,
    const float* __restrict__ bias,
    __half* __restrict__ outh,
    float* __restrict__ outf)
{
    extern __shared__ char sm[];
    __shared__ float s_bias[128];

    const int KTOT = 9 * CIN;
    const int CPP  = CIN / 32;
    const int NT   = 9 * CPP;

    int tid  = threadIdx.x;
    int lane = tid & 31;
    int wid  = tid >> 5;
    int wm   = wid & 1;
    int wn   = wid >> 1;
    int cobase = blockIdx.y * 128;

    if (tid < 128) s_bias[tid] = bias[cobase + tid];

    int fr = tid >> 1;
    int fo = (tid & 1) * 16;
    int p  = blockIdx.x * 128 + fr;
    int fx = p % WOUT;
    int fy = (p / WOUT) % HOUT;
    int fbt = p / (WOUT * HOUT);
    const __half* bsh = wth + (size_t)(cobase + fr) * KTOT + fo;
    const __half* bsl = wtl + (size_t)(cobase + fr) * KTOT + fo;

    uint32_t smb = smem_u32(sm);

    int aoff = ((((lane >> 3) & 1) * 8 + (lane & 7)) * RS) + ((lane >> 4) * 8) * 2;
    int boff = (((lane >> 4) * 8 + (lane & 7)) * RS) + (((lane >> 3) & 1) * 8) * 2;

    float acc[4][4][4];
#pragma unroll
    for (int i = 0; i < 4; i++)
#pragma unroll
        for (int j = 0; j < 4; j++)
#pragma unroll
            for (int k = 0; k < 4; k++) acc[i][j][k] = 0.0f;

    auto FILL = [&](int s, int kt) {
        int pos = kt / CPP, ci0 = (kt - pos * CPP) * 32;
        int dy = pos / 3, dx = pos - dy * 3;
        int iy = 2 * fy + dy, ix = 2 * fx + dx;
        bool valid = (iy < HIN) && (ix < WIN);
        uint32_t vs = valid ? 16u : 0u;
        size_t asrc = valid
            ? ((((size_t)fbt * HIN + iy) * WIN + ix) * CIN + ci0 + fo) : 0;
        uint32_t d = smb + s * STG3 + fr * RS + fo * 2;
        cp16(d,                 in + asrc,         vs);
        cp16(d + 16,            in + asrc + 8,     vs);
        cp16(d + MATB,          bsh + kt * 32,     16u);
        cp16(d + MATB + 16,     bsh + kt * 32 + 8, 16u);
        cp16(d + 2 * MATB,      bsl + kt * 32,     16u);
        cp16(d + 2 * MATB + 16, bsl + kt * 32 + 8, 16u);
    };

    auto COMPUTE = [&](int s) {
        uint32_t ab = smb + s * STG3;
#pragma unroll
        for (int ks = 0; ks < 2; ks++) {
            uint32_t bh[8], bl[8];
#pragma unroll
            for (int q = 0; q < 2; q++) {
                uint32_t ro = boff + (wn * 32 + q * 16) * RS + ks * 32;
                ldmx4(&bh[4 * q], ab + MATB + ro);
                ldmx4(&bl[4 * q], ab + 2 * MATB + ro);
            }
#pragma unroll
            for (int mt = 0; mt < 4; mt++) {
                uint32_t af[4];
                ldmx4(af, ab + aoff + (wm * 64 + mt * 16) * RS + ks * 32);
#pragma unroll
                for (int nt = 0; nt < 4; nt++) mma_f16(acc[mt][nt], af, &bh[2 * nt]);
#pragma unroll
                for (int nt = 0; nt < 4; nt++) mma_f16(acc[mt][nt], af, &bl[2 * nt]);
            }
        }
    };

    FILL(0, 0); CP_COMMIT();
    FILL(1, 1); CP_COMMIT();
#pragma unroll 1
    for (int kt = 0; kt < NT; kt++) {
        if (kt + 1 < NT) { CP_WAIT1(); } else { CP_WAIT0(); }
        __syncthreads();
        if (kt + 2 < NT) { FILL((kt + 2) % 3, kt + 2); CP_COMMIT(); }
        COMPUTE(kt % 3);
    }

    int mrow = blockIdx.x * 128 + wm * 64 + (lane >> 2);
    int cbase = wn * 32 + 2 * (lane & 3);
#pragma unroll
    for (int mt = 0; mt < 4; mt++) {
#pragma unroll
        for (int nt = 0; nt < 4; nt++) {
            int col = cbase + nt * 8;
            float b0 = s_bias[col], b1 = s_bias[col + 1];
            size_t r0 = (size_t)(mrow + mt * 16) * COUT + cobase + col;
            size_t r1 = (size_t)(mrow + mt * 16 + 8) * COUT + cobase + col;
            float a0 = fmaxf(acc[mt][nt][0] + b0, 0.f);
            float a1 = fmaxf(acc[mt][nt][1] + b1, 0.f);
            float a2 = fmaxf(acc[mt][nt][2] + b0, 0.f);
            float a3 = fmaxf(acc[mt][nt][3] + b1, 0.f);
            *reinterpret_cast<uint32_t*>(outh + r0) = packh2(a0, a1);
            *reinterpret_cast<uint32_t*>(outh + r1) = packh2(a2, a3);
            if (WF32) {
                *reinterpret_cast<float2*>(outf + r0) = make_float2(a0, a1);
                *reinterpret_cast<float2*>(outf + r1) = make_float2(a2, a3);
            }
        }
    }
}

// ---------------------------------------------------------------------------
// corr GEMM: D = Q . X^T / 16; Q split hi/lo fp16 (A side), X single fp16.
// ---------------------------------------------------------------------------
__global__ void __launch_bounds__(256, 2) corr_mma_kernel()
{
    extern __shared__ char sm[];

    int tid  = threadIdx.x;
    int lane = tid & 31;
    int wid  = tid >> 5;
    int wm   = wid & 1;
    int wn   = wid >> 1;

    int bt  = blockIdx.z;
    int b   = bt / 24;
    int n0  = blockIdx.y * 128;
    int hw0 = blockIdx.x * 128;

    int fr = tid >> 1;
    int fo = (tid & 1) * 16;
    const __half* ah = g_qh + ((size_t)b * 512 + n0 + fr) * 256 + fo;
    const __half* al = g_ql + ((size_t)b * 512 + n0 + fr) * 256 + fo;
    const __half* bx = g_f3 + ((size_t)bt * 1024 + hw0 + fr) * 256 + fo;

    uint32_t smb = smem_u32(sm);

    int aoff = ((((lane >> 3) & 1) * 8 + (lane & 7)) * RS) + ((lane >> 4) * 8) * 2;
    int boff = (((lane >> 4) * 8 + (lane & 7)) * RS) + (((lane >> 3) & 1) * 8) * 2;

    float acc[4][4][4];
#pragma unroll
    for (int i = 0; i < 4; i++)
#pragma unroll
        for (int j = 0; j < 4; j++)
#pragma unroll
            for (int k = 0; k < 4; k++) acc[i][j][k] = 0.0f;

    auto FILL = [&](int s, int kt) {
        uint32_t d = smb + s * STG3 + fr * RS + fo * 2;
        cp16(d,                 ah + kt * 32,     16u);
        cp16(d + 16,            ah + kt * 32 + 8, 16u);
        cp16(d + MATB,          al + kt * 32,     16u);
        cp16(d + MATB + 16,     al + kt * 32 + 8, 16u);
        cp16(d + 2 * MATB,      bx + kt * 32,     16u);
        cp16(d + 2 * MATB + 16, bx + kt * 32 + 8, 16u);
    };

    auto COMPUTE = [&](int s) {
        uint32_t ab = smb + s * STG3;
#pragma unroll
        for (int ks = 0; ks < 2; ks++) {
            uint32_t bxr[8];
#pragma unroll
            for (int q = 0; q < 2; q++) {
                uint32_t ro = boff + (wn * 32 + q * 16) * RS + ks * 32;
                ldmx4(&bxr[4 * q], ab + 2 * MATB + ro);
            }
#pragma unroll
            for (int mt = 0; mt < 4; mt++) {
                uint32_t af[4];
                uint32_t aaddr = ab + aoff + (wm * 64 + mt * 16) * RS + ks * 32;
                ldmx4(af, aaddr);
#pragma unroll
                for (int nt = 0; nt < 4; nt++) mma_f16(acc[mt][nt], af, &bxr[2 * nt]);
                ldmx4(af, aaddr + MATB);
#pragma unroll
                for (int nt = 0; nt < 4; nt++) mma_f16(acc[mt][nt], af, &bxr[2 * nt]);
            }
        }
    };

    FILL(0, 0); CP_COMMIT();
    FILL(1, 1); CP_COMMIT();
#pragma unroll 1
    for (int kt = 0; kt < 8; kt++) {
        if (kt + 1 < 8) { CP_WAIT1(); } else { CP_WAIT0(); }
        __syncthreads();
        if (kt + 2 < 8) { FILL((kt + 2) % 3, kt + 2); CP_COMMIT(); }
        COMPUTE(kt % 3);
    }

    float* C = g_corr + (size_t)bt * 512 * 1024;
    int mrow = n0 + wm * 64 + (lane >> 2);
    int cbase = hw0 + wn * 32 + 2 * (lane & 3);
#pragma unroll
    for (int mt = 0; mt < 4; mt++) {
#pragma unroll
        for (int nt = 0; nt < 4; nt++) {
            int col = cbase + nt * 8;
            int r0 = mrow + mt * 16;
            float2 o0, o1;
            o0.x = acc[mt][nt][0] * 0.0625f;
            o0.y = acc[mt][nt][1] * 0.0625f;
            o1.x = acc[mt][nt][2] * 0.0625f;
            o1.y = acc[mt][nt][3] * 0.0625f;
            *reinterpret_cast<float2*>(C + (size_t)r0 * 1024 + col) = o0;
            *reinterpret_cast<float2*>(C + (size_t)(r0 + 8) * 1024 + col) = o1;
        }
    }
}

// ---------------------------------------------------------------------------
// Bilinear sampling -> q fp16 hi/lo
// ---------------------------------------------------------------------------
__global__ void __launch_bounds__(256) sample_kernel(const float* __restrict__ qp)
{
    int bn = blockIdx.x;
    float q0 = qp[bn * 3 + 0];
    float q1 = qp[bn * 3 + 1];
    float q2 = qp[bn * 3 + 2];

    int t = (int)(q0 * 23.0f);
    t = min(max(t, 0), 23);
    float yf = q1 * 31.0f;
    float xf = q2 * 31.0f;
    int y0 = min(max((int)floorf(yf), 0), 31);
    int y1 = min(y0 + 1, 31);
    int x0 = min(max((int)floorf(xf), 0), 31);
    int x1 = min(x0 + 1, 31);
    float wy1 = yf - (float)y0, wy0 = 1.0f - wy1;
    float wx1 = xf - (float)x0, wx0 = 1.0f - wx1;

    int b = bn >> 9;
    const float* f = g_feat3 + (size_t)(b * 24 + t) * 1024 * 256;
    int c = threadIdx.x;
    float f00 = f[(size_t)(y0 * 32 + x0) * 256 + c];
    float f01 = f[(size_t)(y0 * 32 + x1) * 256 + c];
    float f10 = f[(size_t)(y1 * 32 + x0) * 256 + c];
    float f11 = f[(size_t)(y1 * 32 + x1) * 256 + c];
    float f0 = f00 * wx0 + f01 * wx1;
    float f1 = f10 * wx0 + f11 * wx1;
    float v = f0 * wy0 + f1 * wy1;
    __half hb = __float2half(v);
    g_qh[(size_t)bn * 256 + c] = hb;
    g_ql[(size_t)bn * 256 + c] = __float2half(v - __half2float(hb));
}

// ---------------------------------------------------------------------------
// Fused softmax(corr*10) expectation + occlusion.
// ---------------------------------------------------------------------------
__global__ void __launch_bounds__(256) finalize_kernel(float* __restrict__ out)
{
    int gwarp = (blockIdx.x * 256 + threadIdx.x) >> 5;
    int lane  = threadIdx.x & 31;

    const float* c = g_corr + (size_t)gwarp * 1024;
    float v[32];
    float m = -1e30f;
#pragma unroll
    for (int i = 0; i < 8; i++) {
        float4 t4 = *reinterpret_cast<const float4*>(&c[i * 128 + lane * 4]);
        v[i * 4 + 0] = t4.x;
        v[i * 4 + 1] = t4.y;
        v[i * 4 + 2] = t4.z;
        v[i * 4 + 3] = t4.w;
        m = fmaxf(m, fmaxf(fmaxf(t4.x, t4.y), fmaxf(t4.z, t4.w)));
    }
#pragma unroll
    for (int o = 16; o > 0; o >>= 1)
        m = fmaxf(m, __shfl_xor_sync(0xffffffffu, m, o));

    float s = 0.0f, sx = 0.0f, sy = 0.0f;
#pragma unroll
    for (int i = 0; i < 8; i++) {
#pragma unroll
        for (int j = 0; j < 4; j++) {
            int idx = i * 128 + lane * 4 + j;
            float e = __expf(10.0f * (v[i * 4 + j] - m));
            s  += e;
            sx += e * (float)(idx & 31);
            sy += e * (float)(idx >> 5);
        }
    }
#pragma unroll
    for (int o = 16; o > 0; o >>= 1) {
        s  += __shfl_xor_sync(0xffffffffu, s, o);
        sx += __shfl_xor_sync(0xffffffffu, sx, o);
        sy += __shfl_xor_sync(0xffffffffu, sy, o);
    }

    if (lane == 0) {
        int bt = gwarp >> 9;
        int n  = gwarp & 511;
        int b  = bt / 24;
        int t  = bt - b * 24;
        int o  = (b * 512 + n) * 24 + t;
        float inv = 8.0f / s;
        out[2 * o + 0] = sx * inv;
        out[2 * o + 1] = sy * inv;
        out[2 * 24576 + o] = 1.0f / (1.0f + __expf(m));
    }
}

// ---------------------------------------------------------------------------
// Launch
// ---------------------------------------------------------------------------
extern "C" void kernel_launch(void* const* d_in, const int* in_sizes, int n_in,
                              void* d_out, int out_size)
{
    const float* video = (const float*)d_in[0];
    const float* qp    = (const float*)d_in[1];
    const float* w1    = (const float*)d_in[2];
    const float* b1    = (const float*)d_in[3];
    const float* w2    = (const float*)d_in[4];
    const float* b2    = (const float*)d_in[5];
    const float* w3    = (const float*)d_in[6];
    const float* b3    = (const float*)d_in[7];

    __half *f1, *f2, *f3, *wt2h, *wt2l, *wt3h, *wt3l;
    float *feat3;
    cudaGetSymbolAddress((void**)&f1, g_f1);
    cudaGetSymbolAddress((void**)&f2, g_f2);
    cudaGetSymbolAddress((void**)&f3, g_f3);
    cudaGetSymbolAddress((void**)&feat3, g_feat3);
    cudaGetSymbolAddress((void**)&wt2h, g_w2h);
    cudaGetSymbolAddress((void**)&wt2l, g_w2l);
    cudaGetSymbolAddress((void**)&wt3h, g_w3h);
    cudaGetSymbolAddress((void**)&wt3l, g_w3l);

    cudaFuncSetAttribute((const void*)conv1_fused_kernel,
                         cudaFuncAttributeMaxDynamicSharedMemorySize, DSMEM_C1);
    cudaFuncSetAttribute(
        (const void*)conv_mma_kernel<64, 128, 128, 128, 64, 64, false>,
        cudaFuncAttributeMaxDynamicSharedMemorySize, DSMEM_CONV);
    cudaFuncSetAttribute(
        (const void*)conv_mma_kernel<128, 256, 64, 64, 32, 32, true>,
        cudaFuncAttributeMaxDynamicSharedMemorySize, DSMEM_CONV);
    cudaFuncSetAttribute((const void*)corr_mma_kernel,
                         cudaFuncAttributeMaxDynamicSharedMemorySize, DSMEM_CONV);

    // weight prep (tiny)
    prep_w1_kernel<<<56, 256>>>(w1);
    transpose_split_w<<<(576 * 128 + 255) / 256, 256>>>(w2, wt2h, wt2l, 576, 128);
    transpose_split_w<<<(1152 * 256 + 255) / 256, 256>>>(w3, wt3h, wt3l, 1152, 256);

    // conv1 fused: one block per (bt, y) output row
    conv1_fused_kernel<<<48 * 128, 256, DSMEM_C1>>>(video, b1);

    // conv2: 196608 px / 128 = 1536 tiles
    conv_mma_kernel<64, 128, 128, 128, 64, 64, false>
        <<<dim3(1536, 1, 1), 256, DSMEM_CONV>>>(f1, wt2h, wt2l, b2, f2, nullptr);

    // conv3: 384 tiles x 2 N-chunks
    conv_mma_kernel<128, 256, 64, 64, 32, 32, true>
        <<<dim3(384, 2, 1), 256, DSMEM_CONV>>>(f2, wt3h, wt3l, b3, f3, feat3);

    // sampling -> q hi/lo
    sample_kernel<<<1024, 256>>>(qp);

    // corr GEMM
    corr_mma_kernel<<<dim3(8, 4, 48), 256, DSMEM_CONV>>>();

    // softmax + expectation + occlusion
    finalize_kernel<<<3072, 256>>>((float*)d_out);
}

// round 9
// speedup vs baseline: 2.6608x; 1.3290x over previous
#include <cuda_runtime.h>
#include <cuda_fp16.h>
#include <math.h>
#include <stdint.h>

// ---------------------------------------------------------------------------
// B=2, T=24, H=256, W=256, N=512, HIDDEN=256
// conv1: FUSED smem-im2col + mma fp16 single-pass          -> feat1 fp16
// conv2: 3x3x64->128 s2  implicit GEMM mma fp16 single     -> feat2 fp16
// conv3: 3x3x128->256 s2 implicit GEMM mma fp16 single     -> feat3 fp32+fp16
// corr : [48] 512x1024x256 GEMM mma fp16 single
// ---------------------------------------------------------------------------

__device__ __half g_f1[2 * 24 * 128 * 128 * 64];          // 100 MB
__device__ __half g_f2[2 * 24 * 64 * 64 * 128];           //  50 MB
__device__ float  g_feat3[2 * 24 * 32 * 32 * 256];        //  50 MB (sampling)
__device__ __half g_f3[2 * 24 * 32 * 32 * 256];           //  25 MB (corr B)
__device__ __half g_qh[2 * 512 * 256];
__device__ float  g_corr[2 * 24 * 512 * 1024];            // 100 MB
__device__ __half g_w1h[64 * 224];                        // conv1 W [cout][224]
__device__ __half g_w2h[128 * 576];
__device__ __half g_w3h[256 * 1152];

// ---------------------------------------------------------------------------
// helpers
// ---------------------------------------------------------------------------
__device__ __forceinline__ uint32_t smem_u32(const void* p) {
    uint32_t a;
    asm("{ .reg .u64 t; cvta.to.shared.u64 t, %1; cvt.u32.u64 %0, t; }"
        : "=r"(a) : "l"(p));
    return a;
}

__device__ __forceinline__ void cp16(uint32_t dst, const void* gsrc, uint32_t ss) {
    asm volatile(
        "{ .reg .u64 g; cvta.to.global.u64 g, %1;"
        "  cp.async.ca.shared.global [%0], [g], 16, %2; }"
        :: "r"(dst), "l"(gsrc), "r"(ss) : "memory");
}
#define CP_COMMIT() asm volatile("cp.async.commit_group;" ::: "memory")
#define CP_WAIT1()  asm volatile("cp.async.wait_group 1;" ::: "memory")
#define CP_WAIT0()  asm volatile("cp.async.wait_group 0;" ::: "memory")

__device__ __forceinline__ void ldmx4(uint32_t* r, uint32_t addr) {
    asm volatile(
        "ldmatrix.sync.aligned.m8n8.x4.shared.b16 {%0,%1,%2,%3}, [%4];"
        : "=r"(r[0]), "=r"(r[1]), "=r"(r[2]), "=r"(r[3]) : "r"(addr));
}

__device__ __forceinline__ void mma_f16(float* d, const uint32_t* a,
                                        const uint32_t* b) {
    asm volatile(
        "mma.sync.aligned.m16n8k16.row.col.f32.f16.f16.f32 "
        "{%0,%1,%2,%3}, {%4,%5,%6,%7}, {%8,%9}, {%0,%1,%2,%3};"
        : "+f"(d[0]), "+f"(d[1]), "+f"(d[2]), "+f"(d[3])
        : "r"(a[0]), "r"(a[1]), "r"(a[2]), "r"(a[3]), "r"(b[0]), "r"(b[1]));
}

__device__ __forceinline__ uint32_t packh2(float a, float b) {
    __half2 t = __floats2half2_rn(a, b);
    return *reinterpret_cast<uint32_t*>(&t);
}

// smem tile: 128 rows x 32 fp16, row stride 80 B (16B pad, conflict-free)
#define RS    80
#define MATB  (128 * RS)            // 10240 B
#define STG2  (2 * MATB)            // A | B (single-pass)
#define DSMEM_CONV (3 * STG2)       // 61440 B, 3-stage pipeline

// conv1 fused smem layout: A double buffer + B(7x64 rows) + V(7 rows)
#define C1_B   (2 * MATB)                 // 20480
#define C1_V   (C1_B + 7 * 64 * RS)       // 56320
#define C1_VROW 1600
#define DSMEM_C1 (C1_V + 7 * C1_VROW)     // 67520

// ---------------------------------------------------------------------------
// conv1 weight prep: w1[(dy*7+dx)*3+ci][64] -> g_w1h[cout][dy*32 + dx*3+ci]
// ---------------------------------------------------------------------------
__global__ void __launch_bounds__(256) prep_w1_kernel(const float* __restrict__ w)
{
    int i = blockIdx.x * 256 + threadIdx.x;   // 64*224
    if (i >= 64 * 224) return;
    int c = i / 224, kk = i - c * 224;
    int dy = kk / 32, r = kk - dy * 32;
    float v = (r < 21) ? w[(dy * 21 + r) * 64 + c] : 0.f;
    g_w1h[i] = __float2half(v);
}

// w[k][cout] -> wt[cout][k] fp16
__global__ void __launch_bounds__(256) transpose_w(
    const float* __restrict__ w, __half* __restrict__ h, int K, int C)
{
    int i = blockIdx.x * 256 + threadIdx.x;
    if (i < K * C) {
        int k = i / C, c = i - k * C;
        h[(size_t)c * K + k] = __float2half(w[i]);
    }
}

// ---------------------------------------------------------------------------
// conv1 fused: one block = one output row (bt, y) = 128 pixels (M), N=64.
// ---------------------------------------------------------------------------
__global__ void __launch_bounds__(256, 3) conv1_fused_kernel(
    const float* __restrict__ video,
    const float* __restrict__ bias)
{
    extern __shared__ char sm[];
    __shared__ float s_bias[64];

    int tid  = threadIdx.x;
    int lane = tid & 31;
    int wid  = tid >> 5;
    int wm   = wid & 3;
    int wn   = wid >> 2;

    int y  = blockIdx.x & 127;
    int bt = blockIdx.x >> 7;

    if (tid < 64) s_bias[tid] = bias[tid];

    uint32_t smb = smem_u32(sm);

    // B preload: 7 chunks x 64 rows x 4 segs = 1792 cp16
    for (int u = tid; u < 1792; u += 256) {
        int seg = u & 3;
        int cc  = (u >> 2) % 7;
        int r   = u / 28;
        const __half* s = g_w1h + r * 224 + cc * 32 + seg * 8;
        uint32_t d = smb + C1_B + (cc * 64 + r) * RS + seg * 16;
        cp16(d, s, 16u);
    }
    CP_COMMIT();

    // zero video smem (incl. halos)
    uint32_t* vz = reinterpret_cast<uint32_t*>(sm + C1_V);
    for (int u = tid; u < 7 * C1_VROW / 4; u += 256) vz[u] = 0u;
    __syncthreads();

    // video rows: dy in [0,7), iy = 2y+dy-2; 768 floats -> halfs [6..773]
    const float inv255 = 1.0f / 255.0f;
    for (int u = tid; u < 7 * 384; u += 256) {
        int dy = u / 384;
        int m  = u - dy * 384;
        int iy = 2 * y + dy - 2;
        if ((unsigned)iy < 256u) {
            const float2 v2 = *reinterpret_cast<const float2*>(
                video + ((size_t)(bt * 256 + iy) * 256) * 3 + 2 * m);
            uint32_t pk = packh2(v2.x * inv255, v2.y * inv255);
            *reinterpret_cast<uint32_t*>(sm + C1_V + dy * C1_VROW + 12 + 4 * m) = pk;
        }
    }
    CP_WAIT0();
    __syncthreads();

    int fr = tid >> 1;
    int fo = (tid & 1) * 16;

    auto BUILD = [&](int s, int dy) {
        const uint32_t* src = reinterpret_cast<const uint32_t*>(
            sm + C1_V + dy * C1_VROW + (6 * fr + fo) * 2);
        uint32_t* dst = reinterpret_cast<uint32_t*>(
            sm + s * MATB + fr * RS + fo * 2);
#pragma unroll
        for (int j = 0; j < 8; j++) dst[j] = src[j];
    };

    int aoff = ((((lane >> 3) & 1) * 8 + (lane & 7)) * RS) + ((lane >> 4) * 8) * 2;
    int boff = (((lane >> 4) * 8 + (lane & 7)) * RS) + (((lane >> 3) & 1) * 8) * 2;

    float acc[2][4][4];
#pragma unroll
    for (int i = 0; i < 2; i++)
#pragma unroll
        for (int j = 0; j < 4; j++)
#pragma unroll
            for (int k = 0; k < 4; k++) acc[i][j][k] = 0.0f;

    auto COMPUTE = [&](int s, int cc) {
        uint32_t ab = smb + s * MATB;
        uint32_t bb = smb + C1_B + cc * (64 * RS);
#pragma unroll
        for (int ks = 0; ks < 2; ks++) {
            uint32_t bh[8];
#pragma unroll
            for (int q = 0; q < 2; q++) {
                uint32_t ro = boff + (wn * 32 + q * 16) * RS + ks * 32;
                ldmx4(&bh[4 * q], bb + ro);
            }
#pragma unroll
            for (int mt = 0; mt < 2; mt++) {
                uint32_t af[4];
                ldmx4(af, ab + aoff + (wm * 32 + mt * 16) * RS + ks * 32);
#pragma unroll
                for (int nt = 0; nt < 4; nt++) mma_f16(acc[mt][nt], af, &bh[2 * nt]);
            }
        }
    };

    BUILD(0, 0);
    __syncthreads();
#pragma unroll 1
    for (int cc = 0; cc < 7; cc++) {
        if (cc + 1 < 7) BUILD((cc + 1) & 1, cc + 1);
        COMPUTE(cc & 1, cc);
        __syncthreads();
    }

    int mrow = blockIdx.x * 128 + wm * 32 + (lane >> 2);
    int cbase = wn * 32 + 2 * (lane & 3);
#pragma unroll
    for (int mt = 0; mt < 2; mt++) {
#pragma unroll
        for (int nt = 0; nt < 4; nt++) {
            int col = cbase + nt * 8;
            float b0 = s_bias[col], b1 = s_bias[col + 1];
            size_t r0 = (size_t)(mrow + mt * 16) * 64 + col;
            size_t r1 = (size_t)(mrow + mt * 16 + 8) * 64 + col;
            float a0 = fmaxf(acc[mt][nt][0] + b0, 0.f);
            float a1 = fmaxf(acc[mt][nt][1] + b1, 0.f);
            float a2 = fmaxf(acc[mt][nt][2] + b0, 0.f);
            float a3 = fmaxf(acc[mt][nt][3] + b1, 0.f);
            *reinterpret_cast<uint32_t*>(g_f1 + r0) = packh2(a0, a1);
            *reinterpret_cast<uint32_t*>(g_f1 + r1) = packh2(a2, a3);
        }
    }
}

// ---------------------------------------------------------------------------
// Implicit-GEMM 3x3 s2 conv, fp16 single-pass.
// Block tile 128 x 128, K chunk 32, 8 warps (2M x 4N), 3-stage cp.async.
// ---------------------------------------------------------------------------
template <int CIN, int COUT, int HIN, int WIN, int HOUT, int WOUT, bool WF32>
__global__ void __launch_bounds__(256, 2) conv_mma_kernel(
    const __half* __restrict__ in,
    const __half* __restrict__ wth,
    const float* __restrict__ bias,
    __half* __restrict__ outh,
    float* __restrict__ outf)
{
    extern __shared__ char sm[];
    __shared__ float s_bias[128];

    const int KTOT = 9 * CIN;
    const int CPP  = CIN / 32;
    const int NT   = 9 * CPP;

    int tid  = threadIdx.x;
    int lane = tid & 31;
    int wid  = tid >> 5;
    int wm   = wid & 1;
    int wn   = wid >> 1;
    int cobase = blockIdx.y * 128;

    if (tid < 128) s_bias[tid] = bias[cobase + tid];

    int fr = tid >> 1;
    int fo = (tid & 1) * 16;
    int p  = blockIdx.x * 128 + fr;
    int fx = p % WOUT;
    int fy = (p / WOUT) % HOUT;
    int fbt = p / (WOUT * HOUT);
    const __half* bsh = wth + (size_t)(cobase + fr) * KTOT + fo;

    uint32_t smb = smem_u32(sm);

    int aoff = ((((lane >> 3) & 1) * 8 + (lane & 7)) * RS) + ((lane >> 4) * 8) * 2;
    int boff = (((lane >> 4) * 8 + (lane & 7)) * RS) + (((lane >> 3) & 1) * 8) * 2;

    float acc[4][4][4];
#pragma unroll
    for (int i = 0; i < 4; i++)
#pragma unroll
        for (int j = 0; j < 4; j++)
#pragma unroll
            for (int k = 0; k < 4; k++) acc[i][j][k] = 0.0f;

    auto FILL = [&](int s, int kt) {
        int pos = kt / CPP, ci0 = (kt - pos * CPP) * 32;
        int dy = pos / 3, dx = pos - dy * 3;
        int iy = 2 * fy + dy, ix = 2 * fx + dx;
        bool valid = (iy < HIN) && (ix < WIN);
        uint32_t vs = valid ? 16u : 0u;
        size_t asrc = valid
            ? ((((size_t)fbt * HIN + iy) * WIN + ix) * CIN + ci0 + fo) : 0;
        uint32_t d = smb + s * STG2 + fr * RS + fo * 2;
        cp16(d,             in + asrc,         vs);
        cp16(d + 16,        in + asrc + 8,     vs);
        cp16(d + MATB,      bsh + kt * 32,     16u);
        cp16(d + MATB + 16, bsh + kt * 32 + 8, 16u);
    };

    auto COMPUTE = [&](int s) {
        uint32_t ab = smb + s * STG2;
#pragma unroll
        for (int ks = 0; ks < 2; ks++) {
            uint32_t bh[8];
#pragma unroll
            for (int q = 0; q < 2; q++) {
                uint32_t ro = boff + (wn * 32 + q * 16) * RS + ks * 32;
                ldmx4(&bh[4 * q], ab + MATB + ro);
            }
#pragma unroll
            for (int mt = 0; mt < 4; mt++) {
                uint32_t af[4];
                ldmx4(af, ab + aoff + (wm * 64 + mt * 16) * RS + ks * 32);
#pragma unroll
                for (int nt = 0; nt < 4; nt++) mma_f16(acc[mt][nt], af, &bh[2 * nt]);
            }
        }
    };

    FILL(0, 0); CP_COMMIT();
    FILL(1, 1); CP_COMMIT();
#pragma unroll 1
    for (int kt = 0; kt < NT; kt++) {
        if (kt + 1 < NT) { CP_WAIT1(); } else { CP_WAIT0(); }
        __syncthreads();
        if (kt + 2 < NT) { FILL((kt + 2) % 3, kt + 2); CP_COMMIT(); }
        COMPUTE(kt % 3);
    }

    int mrow = blockIdx.x * 128 + wm * 64 + (lane >> 2);
    int cbase = wn * 32 + 2 * (lane & 3);
#pragma unroll
    for (int mt = 0; mt < 4; mt++) {
#pragma unroll
        for (int nt = 0; nt < 4; nt++) {
            int col = cbase + nt * 8;
            float b0 = s_bias[col], b1 = s_bias[col + 1];
            size_t r0 = (size_t)(mrow + mt * 16) * COUT + cobase + col;
            size_t r1 = (size_t)(mrow + mt * 16 + 8) * COUT + cobase + col;
            float a0 = fmaxf(acc[mt][nt][0] + b0, 0.f);
            float a1 = fmaxf(acc[mt][nt][1] + b1, 0.f);
            float a2 = fmaxf(acc[mt][nt][2] + b0, 0.f);
            float a3 = fmaxf(acc[mt][nt][3] + b1, 0.f);
            *reinterpret_cast<uint32_t*>(outh + r0) = packh2(a0, a1);
            *reinterpret_cast<uint32_t*>(outh + r1) = packh2(a2, a3);
            if (WF32) {
                *reinterpret_cast<float2*>(outf + r0) = make_float2(a0, a1);
                *reinterpret_cast<float2*>(outf + r1) = make_float2(a2, a3);
            }
        }
    }
}

// ---------------------------------------------------------------------------
// corr GEMM: D = Q . X^T / 16; all single fp16.
// ---------------------------------------------------------------------------
__global__ void __launch_bounds__(256, 2) corr_mma_kernel()
{
    extern __shared__ char sm[];

    int tid  = threadIdx.x;
    int lane = tid & 31;
    int wid  = tid >> 5;
    int wm   = wid & 1;
    int wn   = wid >> 1;

    int bt  = blockIdx.z;
    int b   = bt / 24;
    int n0  = blockIdx.y * 128;
    int hw0 = blockIdx.x * 128;

    int fr = tid >> 1;
    int fo = (tid & 1) * 16;
    const __half* ah = g_qh + ((size_t)b * 512 + n0 + fr) * 256 + fo;
    const __half* bx = g_f3 + ((size_t)bt * 1024 + hw0 + fr) * 256 + fo;

    uint32_t smb = smem_u32(sm);

    int aoff = ((((lane >> 3) & 1) * 8 + (lane & 7)) * RS) + ((lane >> 4) * 8) * 2;
    int boff = (((lane >> 4) * 8 + (lane & 7)) * RS) + (((lane >> 3) & 1) * 8) * 2;

    float acc[4][4][4];
#pragma unroll
    for (int i = 0; i < 4; i++)
#pragma unroll
        for (int j = 0; j < 4; j++)
#pragma unroll
            for (int k = 0; k < 4; k++) acc[i][j][k] = 0.0f;

    auto FILL = [&](int s, int kt) {
        uint32_t d = smb + s * STG2 + fr * RS + fo * 2;
        cp16(d,             ah + kt * 32,     16u);
        cp16(d + 16,        ah + kt * 32 + 8, 16u);
        cp16(d + MATB,      bx + kt * 32,     16u);
        cp16(d + MATB + 16, bx + kt * 32 + 8, 16u);
    };

    auto COMPUTE = [&](int s) {
        uint32_t ab = smb + s * STG2;
#pragma unroll
        for (int ks = 0; ks < 2; ks++) {
            uint32_t bxr[8];
#pragma unroll
            for (int q = 0; q < 2; q++) {
                uint32_t ro = boff + (wn * 32 + q * 16) * RS + ks * 32;
                ldmx4(&bxr[4 * q], ab + MATB + ro);
            }
#pragma unroll
            for (int mt = 0; mt < 4; mt++) {
                uint32_t af[4];
                ldmx4(af, ab + aoff + (wm * 64 + mt * 16) * RS + ks * 32);
#pragma unroll
                for (int nt = 0; nt < 4; nt++) mma_f16(acc[mt][nt], af, &bxr[2 * nt]);
            }
        }
    };

    FILL(0, 0); CP_COMMIT();
    FILL(1, 1); CP_COMMIT();
#pragma unroll 1
    for (int kt = 0; kt < 8; kt++) {
        if (kt + 1 < 8) { CP_WAIT1(); } else { CP_WAIT0(); }
        __syncthreads();
        if (kt + 2 < 8) { FILL((kt + 2) % 3, kt + 2); CP_COMMIT(); }
        COMPUTE(kt % 3);
    }

    float* C = g_corr + (size_t)bt * 512 * 1024;
    int mrow = n0 + wm * 64 + (lane >> 2);
    int cbase = hw0 + wn * 32 + 2 * (lane & 3);
#pragma unroll
    for (int mt = 0; mt < 4; mt++) {
#pragma unroll
        for (int nt = 0; nt < 4; nt++) {
            int col = cbase + nt * 8;
            int r0 = mrow + mt * 16;
            float2 o0, o1;
            o0.x = acc[mt][nt][0] * 0.0625f;
            o0.y = acc[mt][nt][1] * 0.0625f;
            o1.x = acc[mt][nt][2] * 0.0625f;
            o1.y = acc[mt][nt][3] * 0.0625f;
            *reinterpret_cast<float2*>(C + (size_t)r0 * 1024 + col) = o0;
            *reinterpret_cast<float2*>(C + (size_t)(r0 + 8) * 1024 + col) = o1;
        }
    }
}

// ---------------------------------------------------------------------------
// Bilinear sampling -> q fp16
// ---------------------------------------------------------------------------
__global__ void __launch_bounds__(256) sample_kernel(const float* __restrict__ qp)
{
    int bn = blockIdx.x;
    float q0 = qp[bn * 3 + 0];
    float q1 = qp[bn * 3 + 1];
    float q2 = qp[bn * 3 + 2];

    int t = (int)(q0 * 23.0f);
    t = min(max(t, 0), 23);
    float yf = q1 * 31.0f;
    float xf = q2 * 31.0f;
    int y0 = min(max((int)floorf(yf), 0), 31);
    int y1 = min(y0 + 1, 31);
    int x0 = min(max((int)floorf(xf), 0), 31);
    int x1 = min(x0 + 1, 31);
    float wy1 = yf - (float)y0, wy0 = 1.0f - wy1;
    float wx1 = xf - (float)x0, wx0 = 1.0f - wx1;

    int b = bn >> 9;
    const float* f = g_feat3 + (size_t)(b * 24 + t) * 1024 * 256;
    int c = threadIdx.x;
    float f00 = f[(size_t)(y0 * 32 + x0) * 256 + c];
    float f01 = f[(size_t)(y0 * 32 + x1) * 256 + c];
    float f10 = f[(size_t)(y1 * 32 + x0) * 256 + c];
    float f11 = f[(size_t)(y1 * 32 + x1) * 256 + c];
    float f0 = f00 * wx0 + f01 * wx1;
    float f1 = f10 * wx0 + f11 * wx1;
    float v = f0 * wy0 + f1 * wy1;
    g_qh[(size_t)bn * 256 + c] = __float2half(v);
}

// ---------------------------------------------------------------------------
// Fused softmax(corr*10) expectation + occlusion.
// ---------------------------------------------------------------------------
__global__ void __launch_bounds__(256) finalize_kernel(float* __restrict__ out)
{
    int gwarp = (blockIdx.x * 256 + threadIdx.x) >> 5;
    int lane  = threadIdx.x & 31;

    const float* c = g_corr + (size_t)gwarp * 1024;
    float v[32];
    float m = -1e30f;
#pragma unroll
    for (int i = 0; i < 8; i++) {
        float4 t4 = *reinterpret_cast<const float4*>(&c[i * 128 + lane * 4]);
        v[i * 4 + 0] = t4.x;
        v[i * 4 + 1] = t4.y;
        v[i * 4 + 2] = t4.z;
        v[i * 4 + 3] = t4.w;
        m = fmaxf(m, fmaxf(fmaxf(t4.x, t4.y), fmaxf(t4.z, t4.w)));
    }
#pragma unroll
    for (int o = 16; o > 0; o >>= 1)
        m = fmaxf(m, __shfl_xor_sync(0xffffffffu, m, o));

    float s = 0.0f, sx = 0.0f, sy = 0.0f;
#pragma unroll
    for (int i = 0; i < 8; i++) {
#pragma unroll
        for (int j = 0; j < 4; j++) {
            int idx = i * 128 + lane * 4 + j;
            float e = __expf(10.0f * (v[i * 4 + j] - m));
            s  += e;
            sx += e * (float)(idx & 31);
            sy += e * (float)(idx >> 5);
        }
    }
#pragma unroll
    for (int o = 16; o > 0; o >>= 1) {
        s  += __shfl_xor_sync(0xffffffffu, s, o);
        sx += __shfl_xor_sync(0xffffffffu, sx, o);
        sy += __shfl_xor_sync(0xffffffffu, sy, o);
    }

    if (lane == 0) {
        int bt = gwarp >> 9;
        int n  = gwarp & 511;
        int b  = bt / 24;
        int t  = bt - b * 24;
        int o  = (b * 512 + n) * 24 + t;
        float inv = 8.0f / s;
        out[2 * o + 0] = sx * inv;
        out[2 * o + 1] = sy * inv;
        out[2 * 24576 + o] = 1.0f / (1.0f + __expf(m));
    }
}

// ---------------------------------------------------------------------------
// Launch
// ---------------------------------------------------------------------------
extern "C" void kernel_launch(void* const* d_in, const int* in_sizes, int n_in,
                              void* d_out, int out_size)
{
    const float* video = (const float*)d_in[0];
    const float* qp    = (const float*)d_in[1];
    const float* w1    = (const float*)d_in[2];
    const float* b1    = (const float*)d_in[3];
    const float* w2    = (const float*)d_in[4];
    const float* b2    = (const float*)d_in[5];
    const float* w3    = (const float*)d_in[6];
    const float* b3    = (const float*)d_in[7];

    __half *f1, *f2, *f3, *wt2h, *wt3h;
    float *feat3;
    cudaGetSymbolAddress((void**)&f1, g_f1);
    cudaGetSymbolAddress((void**)&f2, g_f2);
    cudaGetSymbolAddress((void**)&f3, g_f3);
    cudaGetSymbolAddress((void**)&feat3, g_feat3);
    cudaGetSymbolAddress((void**)&wt2h, g_w2h);
    cudaGetSymbolAddress((void**)&wt3h, g_w3h);

    cudaFuncSetAttribute((const void*)conv1_fused_kernel,
                         cudaFuncAttributeMaxDynamicSharedMemorySize, DSMEM_C1);
    cudaFuncSetAttribute(
        (const void*)conv_mma_kernel<64, 128, 128, 128, 64, 64, false>,
        cudaFuncAttributeMaxDynamicSharedMemorySize, DSMEM_CONV);
    cudaFuncSetAttribute(
        (const void*)conv_mma_kernel<128, 256, 64, 64, 32, 32, true>,
        cudaFuncAttributeMaxDynamicSharedMemorySize, DSMEM_CONV);
    cudaFuncSetAttribute((const void*)corr_mma_kernel,
                         cudaFuncAttributeMaxDynamicSharedMemorySize, DSMEM_CONV);

    // weight prep (tiny)
    prep_w1_kernel<<<56, 256>>>(w1);
    transpose_w<<<(576 * 128 + 255) / 256, 256>>>(w2, wt2h, 576, 128);
    transpose_w<<<(1152 * 256 + 255) / 256, 256>>>(w3, wt3h, 1152, 256);

    // conv1 fused: one block per (bt, y) output row
    conv1_fused_kernel<<<48 * 128, 256, DSMEM_C1>>>(video, b1);

    // conv2: 196608 px / 128 = 1536 tiles
    conv_mma_kernel<64, 128, 128, 128, 64, 64, false>
        <<<dim3(1536, 1, 1), 256, DSMEM_CONV>>>(f1, wt2h, b2, f2, nullptr);

    // conv3: 384 tiles x 2 N-chunks
    conv_mma_kernel<128, 256, 64, 64, 32, 32, true>
        <<<dim3(384, 2, 1), 256, DSMEM_CONV>>>(f2, wt3h, b3, f3, feat3);

    // sampling -> q fp16
    sample_kernel<<<1024, 256>>>(qp);

    // corr GEMM
    corr_mma_kernel<<<dim3(8, 4, 48), 256, DSMEM_CONV>>>();

    // softmax + expectation + occlusion
    finalize_kernel<<<3072, 256>>>((float*)d_out);
}

// round 10
// speedup vs baseline: 2.6748x; 1.0053x over previous
#include <cuda_runtime.h>
#include <cuda_fp16.h>
#include <math.h>
#include <stdint.h>

// ---------------------------------------------------------------------------
// B=2, T=24, H=256, W=256, N=512, HIDDEN=256
// conv1: FUSED smem-im2col + mma fp16, 2 output rows/block  -> feat1 fp16
// conv2: 3x3x64->128 s2  implicit GEMM mma fp16 single      -> feat2 fp16
// conv3: 3x3x128->256 s2 implicit GEMM mma fp16 single      -> feat3 fp16
// corr : [48] 512x1024x256 GEMM mma fp16 single
// ---------------------------------------------------------------------------

__device__ __half g_f1[2 * 24 * 128 * 128 * 64];          // 100 MB
__device__ __half g_f2[2 * 24 * 64 * 64 * 128];           //  50 MB
__device__ __half g_f3[2 * 24 * 32 * 32 * 256];           //  25 MB
__device__ __half g_qh[2 * 512 * 256];
__device__ float  g_corr[2 * 24 * 512 * 1024];            // 100 MB
__device__ __half g_w1h[64 * 224];                        // conv1 W [cout][224]
__device__ __half g_w2h[128 * 576];
__device__ __half g_w3h[256 * 1152];

// ---------------------------------------------------------------------------
// helpers
// ---------------------------------------------------------------------------
__device__ __forceinline__ uint32_t smem_u32(const void* p) {
    uint32_t a;
    asm("{ .reg .u64 t; cvta.to.shared.u64 t, %1; cvt.u32.u64 %0, t; }"
        : "=r"(a) : "l"(p));
    return a;
}

__device__ __forceinline__ void cp16(uint32_t dst, const void* gsrc, uint32_t ss) {
    asm volatile(
        "{ .reg .u64 g; cvta.to.global.u64 g, %1;"
        "  cp.async.ca.shared.global [%0], [g], 16, %2; }"
        :: "r"(dst), "l"(gsrc), "r"(ss) : "memory");
}
#define CP_COMMIT() asm volatile("cp.async.commit_group;" ::: "memory")
#define CP_WAIT1()  asm volatile("cp.async.wait_group 1;" ::: "memory")
#define CP_WAIT0()  asm volatile("cp.async.wait_group 0;" ::: "memory")

__device__ __forceinline__ void ldmx4(uint32_t* r, uint32_t addr) {
    asm volatile(
        "ldmatrix.sync.aligned.m8n8.x4.shared.b16 {%0,%1,%2,%3}, [%4];"
        : "=r"(r[0]), "=r"(r[1]), "=r"(r[2]), "=r"(r[3]) : "r"(addr));
}

__device__ __forceinline__ void mma_f16(float* d, const uint32_t* a,
                                        const uint32_t* b) {
    asm volatile(
        "mma.sync.aligned.m16n8k16.row.col.f32.f16.f16.f32 "
        "{%0,%1,%2,%3}, {%4,%5,%6,%7}, {%8,%9}, {%0,%1,%2,%3};"
        : "+f"(d[0]), "+f"(d[1]), "+f"(d[2]), "+f"(d[3])
        : "r"(a[0]), "r"(a[1]), "r"(a[2]), "r"(a[3]), "r"(b[0]), "r"(b[1]));
}

__device__ __forceinline__ uint32_t packh2(float a, float b) {
    __half2 t = __floats2half2_rn(a, b);
    return *reinterpret_cast<uint32_t*>(&t);
}

// smem tile: rows x 32 fp16, row stride 80 B (16B pad, conflict-free ldmatrix)
#define RS    80
#define MATB  (128 * RS)            // 10240 B (128-row tile)
#define STG2  (2 * MATB)            // A | B (single-pass)
#define DSMEM_CONV (3 * STG2)       // 61440 B, 3-stage pipeline

// conv1 fused (2 rows/block): A 256-row double buffer + B + 9 video rows
#define C1_AST (256 * RS)                 // 20480 per stage
#define C1_B   (2 * C1_AST)               // 40960
#define C1_V   (C1_B + 7 * 64 * RS)       // 76800
#define C1_VROW 1600
#define DSMEM_C1 (C1_V + 9 * C1_VROW)     // 91200

// ---------------------------------------------------------------------------
// conv1 weight prep: w1[(dy*7+dx)*3+ci][64] -> g_w1h[cout][dy*32 + dx*3+ci]
// ---------------------------------------------------------------------------
__global__ void __launch_bounds__(256) prep_w1_kernel(const float* __restrict__ w)
{
    int i = blockIdx.x * 256 + threadIdx.x;   // 64*224
    if (i >= 64 * 224) return;
    int c = i / 224, kk = i - c * 224;
    int dy = kk / 32, r = kk - dy * 32;
    float v = (r < 21) ? w[(dy * 21 + r) * 64 + c] : 0.f;
    g_w1h[i] = __float2half(v);
}

// w[k][cout] -> wt[cout][k] fp16
__global__ void __launch_bounds__(256) transpose_w(
    const float* __restrict__ w, __half* __restrict__ h, int K, int C)
{
    int i = blockIdx.x * 256 + threadIdx.x;
    if (i < K * C) {
        int k = i / C, c = i - k * C;
        h[(size_t)c * K + k] = __float2half(w[i]);
    }
}

// ---------------------------------------------------------------------------
// conv1 fused: one block = TWO output rows (bt, yp..yp+1) = 256 pixels (M).
// N=64 couts. 8 warps = 4M x 2N, warp tile 64x32. 9 video rows shared.
// ---------------------------------------------------------------------------
__global__ void __launch_bounds__(256, 2) conv1_fused_kernel(
    const float* __restrict__ video,
    const float* __restrict__ bias)
{
    extern __shared__ char sm[];
    __shared__ float s_bias[64];

    int tid  = threadIdx.x;
    int lane = tid & 31;
    int wid  = tid >> 5;
    int wm   = wid & 3;          // 4 M-warps (64 rows each)
    int wn   = wid >> 2;         // 2 N-warps (32 cols each)

    int yp = (blockIdx.x & 63) * 2;   // first output row
    int bt = blockIdx.x >> 6;

    if (tid < 64) s_bias[tid] = bias[tid];

    uint32_t smb = smem_u32(sm);

    // B preload: 7 chunks x 64 rows x 4 segs = 1792 cp16
    for (int u = tid; u < 1792; u += 256) {
        int seg = u & 3;
        int cc  = (u >> 2) % 7;
        int r   = u / 28;
        const __half* s = g_w1h + r * 224 + cc * 32 + seg * 8;
        uint32_t d = smb + C1_B + (cc * 64 + r) * RS + seg * 16;
        cp16(d, s, 16u);
    }
    CP_COMMIT();

    // zero video smem (incl. halos): 9 rows
    uint32_t* vz = reinterpret_cast<uint32_t*>(sm + C1_V);
    for (int u = tid; u < 9 * C1_VROW / 4; u += 256) vz[u] = 0u;
    __syncthreads();

    // video rows j=0..8: iy = 2*yp + j - 2; 768 floats -> halfs slot [6..773]
    const float inv255 = 1.0f / 255.0f;
    for (int u = tid; u < 9 * 384; u += 256) {
        int j = u / 384;
        int m = u - j * 384;
        int iy = 2 * yp + j - 2;
        if ((unsigned)iy < 256u) {
            const float2 v2 = *reinterpret_cast<const float2*>(
                video + ((size_t)(bt * 256 + iy) * 256) * 3 + 2 * m);
            uint32_t pk = packh2(v2.x * inv255, v2.y * inv255);
            *reinterpret_cast<uint32_t*>(sm + C1_V + j * C1_VROW + 12 + 4 * m) = pk;
        }
    }
    CP_WAIT0();
    __syncthreads();

    // A build: 2 passes; pass p -> tile row r = (tid>>1) + 128p;
    // x = r & 127, srow = r >> 7, video row j = dy + 2*srow.
    auto BUILD = [&](int s, int dy) {
#pragma unroll
        for (int p = 0; p < 2; p++) {
            int r = (tid >> 1) + 128 * p;
            int x = r & 127;
            int srow = r >> 7;
            int j = dy + 2 * srow;
            int fo = (tid & 1) * 16;
            const uint32_t* src = reinterpret_cast<const uint32_t*>(
                sm + C1_V + j * C1_VROW + (6 * x + fo) * 2);
            uint32_t* dst = reinterpret_cast<uint32_t*>(
                sm + s * C1_AST + r * RS + fo * 2);
#pragma unroll
            for (int q = 0; q < 8; q++) dst[q] = src[q];
        }
    };

    int aoff = ((((lane >> 3) & 1) * 8 + (lane & 7)) * RS) + ((lane >> 4) * 8) * 2;
    int boff = (((lane >> 4) * 8 + (lane & 7)) * RS) + (((lane >> 3) & 1) * 8) * 2;

    float acc[4][4][4];
#pragma unroll
    for (int i = 0; i < 4; i++)
#pragma unroll
        for (int j = 0; j < 4; j++)
#pragma unroll
            for (int k = 0; k < 4; k++) acc[i][j][k] = 0.0f;

    auto COMPUTE = [&](int s, int cc) {
        uint32_t ab = smb + s * C1_AST;
        uint32_t bb = smb + C1_B + cc * (64 * RS);
#pragma unroll
        for (int ks = 0; ks < 2; ks++) {
            uint32_t bh[8];
#pragma unroll
            for (int q = 0; q < 2; q++) {
                uint32_t ro = boff + (wn * 32 + q * 16) * RS + ks * 32;
                ldmx4(&bh[4 * q], bb + ro);
            }
#pragma unroll
            for (int mt = 0; mt < 4; mt++) {
                uint32_t af[4];
                ldmx4(af, ab + aoff + (wm * 64 + mt * 16) * RS + ks * 32);
#pragma unroll
                for (int nt = 0; nt < 4; nt++) mma_f16(acc[mt][nt], af, &bh[2 * nt]);
            }
        }
    };

    BUILD(0, 0);
    __syncthreads();
#pragma unroll 1
    for (int cc = 0; cc < 7; cc++) {
        if (cc + 1 < 7) BUILD((cc + 1) & 1, cc + 1);
        COMPUTE(cc & 1, cc);
        __syncthreads();
    }

    // epilogue: tile row r maps to pixel p = bt*16384 + yp*128 + r (contiguous)
    size_t pbase = (size_t)bt * 16384 + (size_t)yp * 128;
    int rrow = wm * 64 + (lane >> 2);
    int cbase = wn * 32 + 2 * (lane & 3);
#pragma unroll
    for (int mt = 0; mt < 4; mt++) {
#pragma unroll
        for (int nt = 0; nt < 4; nt++) {
            int col = cbase + nt * 8;
            float b0 = s_bias[col], b1 = s_bias[col + 1];
            size_t r0 = (pbase + rrow + mt * 16) * 64 + col;
            size_t r1 = (pbase + rrow + mt * 16 + 8) * 64 + col;
            float a0 = fmaxf(acc[mt][nt][0] + b0, 0.f);
            float a1 = fmaxf(acc[mt][nt][1] + b1, 0.f);
            float a2 = fmaxf(acc[mt][nt][2] + b0, 0.f);
            float a3 = fmaxf(acc[mt][nt][3] + b1, 0.f);
            *reinterpret_cast<uint32_t*>(g_f1 + r0) = packh2(a0, a1);
            *reinterpret_cast<uint32_t*>(g_f1 + r1) = packh2(a2, a3);
        }
    }
}

// ---------------------------------------------------------------------------
// Implicit-GEMM 3x3 s2 conv, fp16 single-pass.
// Block tile 128 x 128, K chunk 32, 8 warps (2M x 4N), 3-stage cp.async.
// ---------------------------------------------------------------------------
template <int CIN, int COUT, int HIN, int WIN, int HOUT, int WOUT>
__global__ void __launch_bounds__(256, 2) conv_mma_kernel(
    const __half* __restrict__ in,
    const __half* __restrict__ wth,
    const float* __restrict__ bias,
    __half* __restrict__ outh)
{
    extern __shared__ char sm[];
    __shared__ float s_bias[128];

    const int KTOT = 9 * CIN;
    const int CPP  = CIN / 32;
    const int NT   = 9 * CPP;

    int tid  = threadIdx.x;
    int lane = tid & 31;
    int wid  = tid >> 5;
    int wm   = wid & 1;
    int wn   = wid >> 1;
    int cobase = blockIdx.y * 128;

    if (tid < 128) s_bias[tid] = bias[cobase + tid];

    int fr = tid >> 1;
    int fo = (tid & 1) * 16;
    int p  = blockIdx.x * 128 + fr;
    int fx = p % WOUT;
    int fy = (p / WOUT) % HOUT;
    int fbt = p / (WOUT * HOUT);
    const __half* bsh = wth + (size_t)(cobase + fr) * KTOT + fo;

    uint32_t smb = smem_u32(sm);

    int aoff = ((((lane >> 3) & 1) * 8 + (lane & 7)) * RS) + ((lane >> 4) * 8) * 2;
    int boff = (((lane >> 4) * 8 + (lane & 7)) * RS) + (((lane >> 3) & 1) * 8) * 2;

    float acc[4][4][4];
#pragma unroll
    for (int i = 0; i < 4; i++)
#pragma unroll
        for (int j = 0; j < 4; j++)
#pragma unroll
            for (int k = 0; k < 4; k++) acc[i][j][k] = 0.0f;

    auto FILL = [&](int s, int kt) {
        int pos = kt / CPP, ci0 = (kt - pos * CPP) * 32;
        int dy = pos / 3, dx = pos - dy * 3;
        int iy = 2 * fy + dy, ix = 2 * fx + dx;
        bool valid = (iy < HIN) && (ix < WIN);
        uint32_t vs = valid ? 16u : 0u;
        size_t asrc = valid
            ? ((((size_t)fbt * HIN + iy) * WIN + ix) * CIN + ci0 + fo) : 0;
        uint32_t d = smb + s * STG2 + fr * RS + fo * 2;
        cp16(d,             in + asrc,         vs);
        cp16(d + 16,        in + asrc + 8,     vs);
        cp16(d + MATB,      bsh + kt * 32,     16u);
        cp16(d + MATB + 16, bsh + kt * 32 + 8, 16u);
    };

    auto COMPUTE = [&](int s) {
        uint32_t ab = smb + s * STG2;
#pragma unroll
        for (int ks = 0; ks < 2; ks++) {
            uint32_t bh[8];
#pragma unroll
            for (int q = 0; q < 2; q++) {
                uint32_t ro = boff + (wn * 32 + q * 16) * RS + ks * 32;
                ldmx4(&bh[4 * q], ab + MATB + ro);
            }
#pragma unroll
            for (int mt = 0; mt < 4; mt++) {
                uint32_t af[4];
                ldmx4(af, ab + aoff + (wm * 64 + mt * 16) * RS + ks * 32);
#pragma unroll
                for (int nt = 0; nt < 4; nt++) mma_f16(acc[mt][nt], af, &bh[2 * nt]);
            }
        }
    };

    FILL(0, 0); CP_COMMIT();
    FILL(1, 1); CP_COMMIT();
#pragma unroll 1
    for (int kt = 0; kt < NT; kt++) {
        if (kt + 1 < NT) { CP_WAIT1(); } else { CP_WAIT0(); }
        __syncthreads();
        if (kt + 2 < NT) { FILL((kt + 2) % 3, kt + 2); CP_COMMIT(); }
        COMPUTE(kt % 3);
    }

    int mrow = blockIdx.x * 128 + wm * 64 + (lane >> 2);
    int cbase = wn * 32 + 2 * (lane & 3);
#pragma unroll
    for (int mt = 0; mt < 4; mt++) {
#pragma unroll
        for (int nt = 0; nt < 4; nt++) {
            int col = cbase + nt * 8;
            float b0 = s_bias[col], b1 = s_bias[col + 1];
            size_t r0 = (size_t)(mrow + mt * 16) * COUT + cobase + col;
            size_t r1 = (size_t)(mrow + mt * 16 + 8) * COUT + cobase + col;
            float a0 = fmaxf(acc[mt][nt][0] + b0, 0.f);
            float a1 = fmaxf(acc[mt][nt][1] + b1, 0.f);
            float a2 = fmaxf(acc[mt][nt][2] + b0, 0.f);
            float a3 = fmaxf(acc[mt][nt][3] + b1, 0.f);
            *reinterpret_cast<uint32_t*>(outh + r0) = packh2(a0, a1);
            *reinterpret_cast<uint32_t*>(outh + r1) = packh2(a2, a3);
        }
    }
}

// ---------------------------------------------------------------------------
// corr GEMM: D = Q . X^T / 16; all single fp16.
// ---------------------------------------------------------------------------
__global__ void __launch_bounds__(256, 2) corr_mma_kernel()
{
    extern __shared__ char sm[];

    int tid  = threadIdx.x;
    int lane = tid & 31;
    int wid  = tid >> 5;
    int wm   = wid & 1;
    int wn   = wid >> 1;

    int bt  = blockIdx.z;
    int b   = bt / 24;
    int n0  = blockIdx.y * 128;
    int hw0 = blockIdx.x * 128;

    int fr = tid >> 1;
    int fo = (tid & 1) * 16;
    const __half* ah = g_qh + ((size_t)b * 512 + n0 + fr) * 256 + fo;
    const __half* bx = g_f3 + ((size_t)bt * 1024 + hw0 + fr) * 256 + fo;

    uint32_t smb = smem_u32(sm);

    int aoff = ((((lane >> 3) & 1) * 8 + (lane & 7)) * RS) + ((lane >> 4) * 8) * 2;
    int boff = (((lane >> 4) * 8 + (lane & 7)) * RS) + (((lane >> 3) & 1) * 8) * 2;

    float acc[4][4][4];
#pragma unroll
    for (int i = 0; i < 4; i++)
#pragma unroll
        for (int j = 0; j < 4; j++)
#pragma unroll
            for (int k = 0; k < 4; k++) acc[i][j][k] = 0.0f;

    auto FILL = [&](int s, int kt) {
        uint32_t d = smb + s * STG2 + fr * RS + fo * 2;
        cp16(d,             ah + kt * 32,     16u);
        cp16(d + 16,        ah + kt * 32 + 8, 16u);
        cp16(d + MATB,      bx + kt * 32,     16u);
        cp16(d + MATB + 16, bx + kt * 32 + 8, 16u);
    };

    auto COMPUTE = [&](int s) {
        uint32_t ab = smb + s * STG2;
#pragma unroll
        for (int ks = 0; ks < 2; ks++) {
            uint32_t bxr[8];
#pragma unroll
            for (int q = 0; q < 2; q++) {
                uint32_t ro = boff + (wn * 32 + q * 16) * RS + ks * 32;
                ldmx4(&bxr[4 * q], ab + MATB + ro);
            }
#pragma unroll
            for (int mt = 0; mt < 4; mt++) {
                uint32_t af[4];
                ldmx4(af, ab + aoff + (wm * 64 + mt * 16) * RS + ks * 32);
#pragma unroll
                for (int nt = 0; nt < 4; nt++) mma_f16(acc[mt][nt], af, &bxr[2 * nt]);
            }
        }
    };

    FILL(0, 0); CP_COMMIT();
    FILL(1, 1); CP_COMMIT();
#pragma unroll 1
    for (int kt = 0; kt < 8; kt++) {
        if (kt + 1 < 8) { CP_WAIT1(); } else { CP_WAIT0(); }
        __syncthreads();
        if (kt + 2 < 8) { FILL((kt + 2) % 3, kt + 2); CP_COMMIT(); }
        COMPUTE(kt % 3);
    }

    float* C = g_corr + (size_t)bt * 512 * 1024;
    int mrow = n0 + wm * 64 + (lane >> 2);
    int cbase = hw0 + wn * 32 + 2 * (lane & 3);
#pragma unroll
    for (int mt = 0; mt < 4; mt++) {
#pragma unroll
        for (int nt = 0; nt < 4; nt++) {
            int col = cbase + nt * 8;
            int r0 = mrow + mt * 16;
            float2 o0, o1;
            o0.x = acc[mt][nt][0] * 0.0625f;
            o0.y = acc[mt][nt][1] * 0.0625f;
            o1.x = acc[mt][nt][2] * 0.0625f;
            o1.y = acc[mt][nt][3] * 0.0625f;
            *reinterpret_cast<float2*>(C + (size_t)r0 * 1024 + col) = o0;
            *reinterpret_cast<float2*>(C + (size_t)(r0 + 8) * 1024 + col) = o1;
        }
    }
}

// ---------------------------------------------------------------------------
// Bilinear sampling from fp16 feat3 -> q fp16
// ---------------------------------------------------------------------------
__global__ void __launch_bounds__(256) sample_kernel(const float* __restrict__ qp)
{
    int bn = blockIdx.x;
    float q0 = qp[bn * 3 + 0];
    float q1 = qp[bn * 3 + 1];
    float q2 = qp[bn * 3 + 2];

    int t = (int)(q0 * 23.0f);
    t = min(max(t, 0), 23);
    float yf = q1 * 31.0f;
    float xf = q2 * 31.0f;
    int y0 = min(max((int)floorf(yf), 0), 31);
    int y1 = min(y0 + 1, 31);
    int x0 = min(max((int)floorf(xf), 0), 31);
    int x1 = min(x0 + 1, 31);
    float wy1 = yf - (float)y0, wy0 = 1.0f - wy1;
    float wx1 = xf - (float)x0, wx0 = 1.0f - wx1;

    int b = bn >> 9;
    const __half* f = g_f3 + (size_t)(b * 24 + t) * 1024 * 256;
    int c = threadIdx.x;
    float f00 = __half2float(f[(size_t)(y0 * 32 + x0) * 256 + c]);
    float f01 = __half2float(f[(size_t)(y0 * 32 + x1) * 256 + c]);
    float f10 = __half2float(f[(size_t)(y1 * 32 + x0) * 256 + c]);
    float f11 = __half2float(f[(size_t)(y1 * 32 + x1) * 256 + c]);
    float f0 = f00 * wx0 + f01 * wx1;
    float f1 = f10 * wx0 + f11 * wx1;
    float v = f0 * wy0 + f1 * wy1;
    g_qh[(size_t)bn * 256 + c] = __float2half(v);
}

// ---------------------------------------------------------------------------
// Fused softmax(corr*10) expectation + occlusion.
// ---------------------------------------------------------------------------
__global__ void __launch_bounds__(256) finalize_kernel(float* __restrict__ out)
{
    int gwarp = (blockIdx.x * 256 + threadIdx.x) >> 5;
    int lane  = threadIdx.x & 31;

    const float* c = g_corr + (size_t)gwarp * 1024;
    float v[32];
    float m = -1e30f;
#pragma unroll
    for (int i = 0; i < 8; i++) {
        float4 t4 = *reinterpret_cast<const float4*>(&c[i * 128 + lane * 4]);
        v[i * 4 + 0] = t4.x;
        v[i * 4 + 1] = t4.y;
        v[i * 4 + 2] = t4.z;
        v[i * 4 + 3] = t4.w;
        m = fmaxf(m, fmaxf(fmaxf(t4.x, t4.y), fmaxf(t4.z, t4.w)));
    }
#pragma unroll
    for (int o = 16; o > 0; o >>= 1)
        m = fmaxf(m, __shfl_xor_sync(0xffffffffu, m, o));

    float s = 0.0f, sx = 0.0f, sy = 0.0f;
#pragma unroll
    for (int i = 0; i < 8; i++) {
#pragma unroll
        for (int j = 0; j < 4; j++) {
            int idx = i * 128 + lane * 4 + j;
            float e = __expf(10.0f * (v[i * 4 + j] - m));
            s  += e;
            sx += e * (float)(idx & 31);
            sy += e * (float)(idx >> 5);
        }
    }
#pragma unroll
    for (int o = 16; o > 0; o >>= 1) {
        s  += __shfl_xor_sync(0xffffffffu, s, o);
        sx += __shfl_xor_sync(0xffffffffu, sx, o);
        sy += __shfl_xor_sync(0xffffffffu, sy, o);
    }

    if (lane == 0) {
        int bt = gwarp >> 9;
        int n  = gwarp & 511;
        int b  = bt / 24;
        int t  = bt - b * 24;
        int o  = (b * 512 + n) * 24 + t;
        float inv = 8.0f / s;
        out[2 * o + 0] = sx * inv;
        out[2 * o + 1] = sy * inv;
        out[2 * 24576 + o] = 1.0f / (1.0f + __expf(m));
    }
}

// ---------------------------------------------------------------------------
// Launch
// ---------------------------------------------------------------------------
extern "C" void kernel_launch(void* const* d_in, const int* in_sizes, int n_in,
                              void* d_out, int out_size)
{
    const float* video = (const float*)d_in[0];
    const float* qp    = (const float*)d_in[1];
    const float* w1    = (const float*)d_in[2];
    const float* b1    = (const float*)d_in[3];
    const float* w2    = (const float*)d_in[4];
    const float* b2    = (const float*)d_in[5];
    const float* w3    = (const float*)d_in[6];
    const float* b3    = (const float*)d_in[7];

    __half *f1, *f2, *f3, *wt2h, *wt3h;
    cudaGetSymbolAddress((void**)&f1, g_f1);
    cudaGetSymbolAddress((void**)&f2, g_f2);
    cudaGetSymbolAddress((void**)&f3, g_f3);
    cudaGetSymbolAddress((void**)&wt2h, g_w2h);
    cudaGetSymbolAddress((void**)&wt3h, g_w3h);

    cudaFuncSetAttribute((const void*)conv1_fused_kernel,
                         cudaFuncAttributeMaxDynamicSharedMemorySize, DSMEM_C1);
    cudaFuncSetAttribute(
        (const void*)conv_mma_kernel<64, 128, 128, 128, 64, 64>,
        cudaFuncAttributeMaxDynamicSharedMemorySize, DSMEM_CONV);
    cudaFuncSetAttribute(
        (const void*)conv_mma_kernel<128, 256, 64, 64, 32, 32>,
        cudaFuncAttributeMaxDynamicSharedMemorySize, DSMEM_CONV);
    cudaFuncSetAttribute((const void*)corr_mma_kernel,
                         cudaFuncAttributeMaxDynamicSharedMemorySize, DSMEM_CONV);

    // weight prep (tiny)
    prep_w1_kernel<<<56, 256>>>(w1);
    transpose_w<<<(576 * 128 + 255) / 256, 256>>>(w2, wt2h, 576, 128);
    transpose_w<<<(1152 * 256 + 255) / 256, 256>>>(w3, wt3h, 1152, 256);

    // conv1 fused: one block per (bt, row-pair)
    conv1_fused_kernel<<<48 * 64, 256, DSMEM_C1>>>(video, b1);

    // conv2: 196608 px / 128 = 1536 tiles
    conv_mma_kernel<64, 128, 128, 128, 64, 64>
        <<<dim3(1536, 1, 1), 256, DSMEM_CONV>>>(f1, wt2h, b2, f2);

    // conv3: 384 tiles x 2 N-chunks
    conv_mma_kernel<128, 256, 64, 64, 32, 32>
        <<<dim3(384, 2, 1), 256, DSMEM_CONV>>>(f2, wt3h, b3, f3);

    // sampling -> q fp16
    sample_kernel<<<1024, 256>>>(qp);

    // corr GEMM
    corr_mma_kernel<<<dim3(8, 4, 48), 256, DSMEM_CONV>>>();

    // softmax + expectation + occlusion
    finalize_kernel<<<3072, 256>>>((float*)d_out);
}